// round 8
// baseline (speedup 1.0000x reference)
#include <cuda_runtime.h>
#include <cstdint>

// ---------------------------------------------------------------------------
// MultiHeadAttention (B=4, S=2048, D=1024, H=16, DK=64).
// Round 8: attn_scale folded into the attention kernel as a per-CTA tail
// (rides the attn kernel's idle DRAM headroom); dense GEMMs move to a
// 3-stage cp.async pipeline with a single __syncthreads per K-chunk.
// tf32 mma.sync everywhere; polynomial exp on FMA pipe.
// Output layout: d_out = [ x (8,388,608 f32) | attn (268,435,456 f32) ]
// ---------------------------------------------------------------------------

namespace {
constexpr int B  = 4;
constexpr int S  = 2048;
constexpr int D  = 1024;
constexpr int H  = 16;
constexpr int DK = 64;
constexpr size_t QH_ELEMS   = (size_t)B * H * S * DK;        // 8,388,608
constexpr size_t X_ELEMS    = (size_t)B * S * D;             // 8,388,608

// dense-GEMM tiling: CTA 128x128, warp 64x32 (2x4 warps), K-chunk 32,
// THREE cp.async stages, one barrier per chunk.
constexpr int KC  = 32;
constexpr int NCH = D / KC;                 // 32 chunks
constexpr int GST = 36;                     // =4 mod 32 -> conflict-free frags
constexpr int GTILE = 128 * GST;            // words per tile
constexpr int GEMM_SMEM = 6 * GTILE * 4;    // 110,592 B (3 stages x {A,B})

// attention smem layout (uint32 words)
constexpr int AQ_OFF = 0;                  // Qs[128][68] (tf32)
constexpr int AK_OFF = AQ_OFF + 128 * 68;  // Ks[64][68]  (tf32 bits via cp.async)
constexpr int AV_OFF = AK_OFF + 64 * 68;   // Vt[64][68]  (tf32 bits; d rows, key cols)
constexpr int AP_OFF = AV_OFF + 64 * 68;   // Ps[128][68] (tf32)
constexpr int ARS_OFF = AP_OFF + 128 * 68; // rs[2][128] floats
constexpr int AIV_OFF = ARS_OFF + 256;     // sinv[128] floats
constexpr int ATTN_SMEM = (AIV_OFF + 128) * 4;   // 105,984 B
}

// Scratch (allocation-free rule: __device__ globals)
__device__ float g_qh[QH_ELEMS];           // tf32-valued
__device__ float g_kh[QH_ELEMS];           // tf32-valued
__device__ float g_vt[QH_ELEMS];           // tf32-valued; V transposed [bh][d][s]
__device__ float g_ctx[X_ELEMS];           // tf32-valued
__device__ float g_x[X_ELEMS];             // fp32
__device__ float g_wqt[(size_t)D * D];     // Wq^T  [N][K], tf32-valued
__device__ float g_wfct[(size_t)D * D];    // Wfc^T [N][K], tf32-valued

// ---------------------------------------------------------------------------
// helpers
// ---------------------------------------------------------------------------
__device__ __forceinline__ uint32_t smem_to_u32(const void* p) {
    uint32_t a;
    asm("{ .reg .u64 t; cvta.to.shared.u64 t, %1; cvt.u32.u64 %0, t; }"
        : "=r"(a) : "l"(p));
    return a;
}
__device__ __forceinline__ uint32_t f2tf32(float x) {
    uint32_t r;
    asm("cvt.rna.tf32.f32 %0, %1;" : "=r"(r) : "f"(x));
    return r;
}
__device__ __forceinline__ uint32_t tf32b(uint32_t rawbits) {
    return f2tf32(__uint_as_float(rawbits));
}
__device__ __forceinline__ void mma_tf32(float* d, const uint32_t* a, const uint32_t* b) {
    asm volatile(
        "mma.sync.aligned.m16n8k8.row.col.f32.tf32.tf32.f32 "
        "{%0,%1,%2,%3}, {%4,%5,%6,%7}, {%8,%9}, {%0,%1,%2,%3};"
        : "+f"(d[0]), "+f"(d[1]), "+f"(d[2]), "+f"(d[3])
        : "r"(a[0]), "r"(a[1]), "r"(a[2]), "r"(a[3]), "r"(b[0]), "r"(b[1]));
}
__device__ __forceinline__ void cp16(uint32_t dst, const void* src) {
    asm volatile("cp.async.cg.shared.global [%0], [%1], 16;" :: "r"(dst), "l"(src));
}
__device__ __forceinline__ void cp8(uint32_t dst, const void* src) {
    asm volatile("cp.async.ca.shared.global [%0], [%1], 8;" :: "r"(dst), "l"(src));
}
__device__ __forceinline__ void cp_commit() {
    asm volatile("cp.async.commit_group;" ::: "memory");
}
__device__ __forceinline__ void cp_wait0() {
    asm volatile("cp.async.wait_group 0;" ::: "memory");
}
__device__ __forceinline__ void cp_wait1() {
    asm volatile("cp.async.wait_group 1;" ::: "memory");
}
// exp via FMA pipe: magic-number range reduction + deg-5 poly (rel err ~2e-6).
__device__ __forceinline__ float fast_exp(float x) {
    const float L2E = 1.4426950408889634f;
    float t = fmaf(x, L2E, 12582912.0f);
    float n = t - 12582912.0f;
    float f = fmaf(x, L2E, -n);
    float p = 0.0013333558f;
    p = fmaf(p, f, 0.0096181291f);
    p = fmaf(p, f, 0.0555041087f);
    p = fmaf(p, f, 0.2402265069f);
    p = fmaf(p, f, 0.6931471806f);
    p = fmaf(p, f, 1.0f);
    return __int_as_float(__float_as_int(p) + (__float_as_int(t) << 23));
}

// ---------------------------------------------------------------------------
// K0: transpose Wq and Wfc once -> g_wqt / g_wfct (tf32-rounded at store)
// ---------------------------------------------------------------------------
__global__ __launch_bounds__(256) void transpose_kernel(
    const float* __restrict__ Wq, const float* __restrict__ Wfc)
{
    __shared__ float tile[32][33];
    const float* src = blockIdx.z ? Wfc : Wq;
    float*       dst = blockIdx.z ? g_wfct : g_wqt;
    int x = blockIdx.x * 32 + threadIdx.x;
    int y = blockIdx.y * 32 + threadIdx.y;
#pragma unroll
    for (int i = 0; i < 32; i += 8)
        tile[threadIdx.y + i][threadIdx.x] = src[(size_t)(y + i) * D + x];
    __syncthreads();
    int tx = blockIdx.y * 32 + threadIdx.x;
    int ty = blockIdx.x * 32 + threadIdx.y;
#pragma unroll
    for (int i = 0; i < 32; i += 8)
        dst[(size_t)(ty + i) * D + tx] =
            __uint_as_float(f2tf32(tile[threadIdx.x][threadIdx.y + i]));
}

// ---------------------------------------------------------------------------
// K1/K4: tf32 mma.sync GEMM, 3-stage cp.async pipeline, one sync per chunk.
// Y[m,n] = A[m,:] . Bt[n,:]  (+bias[, +resid])
// mode 0: proj layout; z=0,1 -> qh/kh rows; z=2 -> V TRANSPOSED to g_vt.
//         A raw fp32 (cvt at fragment load); outputs tf32-rounded.
// mode 1: fc. A (g_ctx) and B pre-rounded -> no cvts; output fp32 + resid.
// ---------------------------------------------------------------------------
__global__ __launch_bounds__(256) void gemm_mma_kernel(
    const float* __restrict__ A0, const float* __restrict__ A1,
    const float* __restrict__ A2, const float* __restrict__ Bt,
    const float* __restrict__ bias, const float* __restrict__ resid,
    float* __restrict__ O0, float* __restrict__ O1, float* __restrict__ O2,
    int mode)
{
    extern __shared__ uint32_t smu[];
    const uint32_t smem_u = smem_to_u32(smu);

    const int tid  = threadIdx.x;
    const int wid  = tid >> 5, lane = tid & 31;
    const int g    = lane >> 2, tq = lane & 3;
    const int wm   = (wid >> 2) * 64;
    const int wn   = (wid & 3) * 32;
    const int n0   = blockIdx.x * 128;
    const int m0   = blockIdx.y * 128;

    const float* Ap;
    float* Op;
    if (blockIdx.z == 0)      { Ap = A0; Op = O0; }
    else if (blockIdx.z == 1) { Ap = A1; Op = O1; }
    else                      { Ap = A2; Op = O2; }

    float acc[4][4][4];
#pragma unroll
    for (int i = 0; i < 4; i++)
#pragma unroll
        for (int j = 0; j < 4; j++)
#pragma unroll
            for (int r = 0; r < 4; r++) acc[i][j][r] = 0.f;

    // prologue: issue chunks 0 (stage 0) and 1 (stage 1)
#pragma unroll
    for (int c0 = 0; c0 < 2; c0++) {
        const int kt = c0 * KC;
        const uint32_t sbase = smem_u + (uint32_t)(c0 * 2 * GTILE) * 4;
#pragma unroll
        for (int j = 0; j < 8; j++) {
            int idx = tid + j * 256;          // 2048 8B-chunks per tile
            int row = idx >> 4, ch = idx & 15;
            uint32_t off = (uint32_t)(row * GST + ch * 2) * 4;
            cp8(sbase + off,             Ap + (size_t)(m0 + row) * D + kt + ch * 2);
            cp8(sbase + off + GTILE * 4, Bt + (size_t)(n0 + row) * D + kt + ch * 2);
        }
        cp_commit();
    }

    for (int c = 0; c < NCH; c++) {
        const int st = c % 3;
        if (c + 1 < NCH) cp_wait1(); else cp_wait0();
        __syncthreads();   // chunk c resident; all warps done with chunk c-1

        // refill stage (c+2)%3 (consumed at c-1) with chunk c+2 — overlaps MMA
        if (c + 2 < NCH) {
            const int kt = (c + 2) * KC;
            const uint32_t sbase = smem_u + (uint32_t)(((c + 2) % 3) * 2 * GTILE) * 4;
#pragma unroll
            for (int j = 0; j < 8; j++) {
                int idx = tid + j * 256;
                int row = idx >> 4, ch = idx & 15;
                uint32_t off = (uint32_t)(row * GST + ch * 2) * 4;
                cp8(sbase + off,             Ap + (size_t)(m0 + row) * D + kt + ch * 2);
                cp8(sbase + off + GTILE * 4, Bt + (size_t)(n0 + row) * D + kt + ch * 2);
            }
            cp_commit();
        }

        const uint32_t* As = smu + st * 2 * GTILE;
        const uint32_t* Bs = As + GTILE;

#pragma unroll
        for (int ks = 0; ks < KC / 8; ks++) {
            const int kk = ks * 8;
            uint32_t a[4][4], b[4][2];
            if (mode == 0) {
#pragma unroll
                for (int mf = 0; mf < 4; mf++) {
                    const int row = wm + mf * 16 + g;
                    a[mf][0] = tf32b(As[row * GST + kk + tq]);
                    a[mf][1] = tf32b(As[(row + 8) * GST + kk + tq]);
                    a[mf][2] = tf32b(As[row * GST + kk + tq + 4]);
                    a[mf][3] = tf32b(As[(row + 8) * GST + kk + tq + 4]);
                }
            } else {
#pragma unroll
                for (int mf = 0; mf < 4; mf++) {
                    const int row = wm + mf * 16 + g;
                    a[mf][0] = As[row * GST + kk + tq];
                    a[mf][1] = As[(row + 8) * GST + kk + tq];
                    a[mf][2] = As[row * GST + kk + tq + 4];
                    a[mf][3] = As[(row + 8) * GST + kk + tq + 4];
                }
            }
#pragma unroll
            for (int nf = 0; nf < 4; nf++) {
                const int col = wn + nf * 8 + g;
                b[nf][0] = Bs[col * GST + kk + tq];
                b[nf][1] = Bs[col * GST + kk + tq + 4];
            }
#pragma unroll
            for (int mf = 0; mf < 4; mf++)
#pragma unroll
                for (int nf = 0; nf < 4; nf++)
                    mma_tf32(acc[mf][nf], a[mf], b[nf]);
        }
    }

#pragma unroll
    for (int mf = 0; mf < 4; mf++) {
#pragma unroll
        for (int nf = 0; nf < 4; nf++) {
            const int m = m0 + wm + mf * 16 + g;
            const int n = n0 + wn + nf * 8 + tq * 2;
            float bx = bias[n], by = bias[n + 1];
#pragma unroll
            for (int half = 0; half < 2; half++) {
                const int mm = m + half * 8;
                float vx = acc[mf][nf][half * 2 + 0] + bx;
                float vy = acc[mf][nf][half * 2 + 1] + by;
                if (mode == 0) {
                    // outputs feed MMA only -> tf32-round at producer
                    vx = __uint_as_float(f2tf32(vx));
                    vy = __uint_as_float(f2tf32(vy));
                    const int h = n >> 6, dk = n & 63;
                    const int bb_ = mm >> 11, s = mm & 2047;
                    if (blockIdx.z == 2) {
                        float* vtb = &g_vt[(((size_t)bb_ * H + h) * DK + dk) * S + s];
                        vtb[0] = vx;
                        vtb[S] = vy;
                    } else {
                        float2* p = (float2*)&Op[(((size_t)bb_ * H + h) * S + s) * DK + dk];
                        *p = make_float2(vx, vy);
                    }
                } else {
                    const float* rr = resid + (size_t)mm * D + n;
                    float2 r2 = *(const float2*)rr;
                    float2* p = (float2*)&Op[(size_t)mm * D + n];
                    *p = make_float2(vx + r2.x, vy + r2.y);
                }
            }
        }
    }
}

// ---------------------------------------------------------------------------
// K2: attention via tf32 mma.sync, cp.async K/V slid into dead phases,
// plus an in-kernel normalization tail: each CTA rescales its own
// 128-row x 2048-col attn slice by sinv (replaces the attn_scale kernel;
// DRAM traffic rides under this kernel's compute).
// grid (16 q-tiles, 64 bh), block 256. Warp grid 4x2.
// ---------------------------------------------------------------------------
__global__ __launch_bounds__(256, 2) void attn_mma_kernel(float* __restrict__ attn_out)
{
    extern __shared__ uint32_t smu[];
    uint32_t* Qs = smu + AQ_OFF;
    uint32_t* Ks = smu + AK_OFF;
    uint32_t* Vt = smu + AV_OFF;
    uint32_t* Ps = smu + AP_OFF;
    float* rs    = (float*)(smu + ARS_OFF);
    float* sinv  = (float*)(smu + AIV_OFF);
    const uint32_t smem_u = smem_to_u32(smu);
    const uint32_t ks_u = smem_u + AK_OFF * 4;
    const uint32_t vt_u = smem_u + AV_OFF * 4;

    const int bh = blockIdx.y;
    const int q0 = blockIdx.x * 128;
    const int tid = threadIdx.x;
    const int wid = tid >> 5, lane = tid & 31;
    const int g = lane >> 2, tq = lane & 3;
    const int wm = (wid >> 1) * 32;
    const int wn = (wid & 1) * 32;
    const float scale = 0.125f;

    const int frow = tid >> 4, fc4 = tid & 15;     // K/V fill: rows frow + i*16

    // Q tile: g_qh is tf32-valued; *0.125 is exact -> store bits directly
#pragma unroll
    for (int i = 0; i < 8; i++) {
        int f4 = tid + i * 256;
        int row = f4 >> 4, c4 = f4 & 15;
        float4 qv = *(const float4*)&g_qh[((size_t)bh * S + q0 + row) * DK + c4 * 4];
        uint32_t* qd = &Qs[row * 68 + c4 * 4];
        qd[0] = __float_as_uint(qv.x * scale);
        qd[1] = __float_as_uint(qv.y * scale);
        qd[2] = __float_as_uint(qv.z * scale);
        qd[3] = __float_as_uint(qv.w * scale);
    }

    // prologue: issue K(0) then V(0) as separate groups
#pragma unroll
    for (int i = 0; i < 4; i++) {
        int row = frow + i * 16;
        cp16(ks_u + (uint32_t)(row * 68 + fc4 * 4) * 4,
             &g_kh[((size_t)bh * S + row) * DK + fc4 * 4]);
    }
    cp_commit();
#pragma unroll
    for (int i = 0; i < 4; i++) {
        int row = frow + i * 16;
        cp16(vt_u + (uint32_t)(row * 68 + fc4 * 4) * 4,
             &g_vt[((size_t)bh * DK + row) * S + fc4 * 4]);
    }
    cp_commit();

    float cacc[2][4][4];
    float rsum[2][2] = {{0.f, 0.f}, {0.f, 0.f}};
#pragma unroll
    for (int mf = 0; mf < 2; mf++)
#pragma unroll
        for (int nf = 0; nf < 4; nf++)
#pragma unroll
            for (int r = 0; r < 4; r++) cacc[mf][nf][r] = 0.f;

    for (int kt = 0; kt < S / 64; kt++) {
        const int k0 = kt * 64;

        cp_wait1();            // K(kt) arrived (V(kt) may still be in flight)
        __syncthreads();

        // S = Q·K^T  (k = d, 8 steps); operands already tf32
        float sacc[2][4][4];
#pragma unroll
        for (int mf = 0; mf < 2; mf++)
#pragma unroll
            for (int nf = 0; nf < 4; nf++)
#pragma unroll
                for (int r = 0; r < 4; r++) sacc[mf][nf][r] = 0.f;
#pragma unroll
        for (int ks = 0; ks < 8; ks++) {
            const int kk = ks * 8;
            uint32_t a[2][4], b[4][2];
#pragma unroll
            for (int mf = 0; mf < 2; mf++) {
                const int row = wm + mf * 16 + g;
                a[mf][0] = Qs[row * 68 + kk + tq];
                a[mf][1] = Qs[(row + 8) * 68 + kk + tq];
                a[mf][2] = Qs[row * 68 + kk + tq + 4];
                a[mf][3] = Qs[(row + 8) * 68 + kk + tq + 4];
            }
#pragma unroll
            for (int nf = 0; nf < 4; nf++) {
                const int col = wn + nf * 8 + g;
                b[nf][0] = Ks[col * 68 + kk + tq];
                b[nf][1] = Ks[col * 68 + kk + tq + 4];
            }
#pragma unroll
            for (int mf = 0; mf < 2; mf++)
#pragma unroll
                for (int nf = 0; nf < 4; nf++)
                    mma_tf32(sacc[mf][nf], a[mf], b[nf]);
        }

        // exp, rowsum, E -> gmem (unnormalized), P -> smem (tf32)
#pragma unroll
        for (int mf = 0; mf < 2; mf++) {
            const int r0 = wm + mf * 16 + g;
#pragma unroll
            for (int nf = 0; nf < 4; nf++) {
                const int c0 = wn + nf * 8 + tq * 2;
                float e00 = fast_exp(sacc[mf][nf][0]);
                float e01 = fast_exp(sacc[mf][nf][1]);
                float e10 = fast_exp(sacc[mf][nf][2]);
                float e11 = fast_exp(sacc[mf][nf][3]);
                rsum[mf][0] += e00 + e01;
                rsum[mf][1] += e10 + e11;
                *(float2*)&attn_out[((size_t)bh * S + q0 + r0) * S + k0 + c0] =
                    make_float2(e00, e01);
                *(float2*)&attn_out[((size_t)bh * S + q0 + r0 + 8) * S + k0 + c0] =
                    make_float2(e10, e11);
                Ps[r0 * 68 + c0]       = f2tf32(e00);
                Ps[r0 * 68 + c0 + 1]   = f2tf32(e01);
                Ps[(r0 + 8) * 68 + c0]     = f2tf32(e10);
                Ps[(r0 + 8) * 68 + c0 + 1] = f2tf32(e11);
            }
        }

        cp_wait0();            // V(kt) arrived
        __syncthreads();       // publish V + Ps; Ks fully consumed

        // issue K(kt+1) into Ks — overlaps the P·V phase below
        if (kt + 1 < S / 64) {
            const int nk0 = k0 + 64;
#pragma unroll
            for (int i = 0; i < 4; i++) {
                int row = frow + i * 16;
                cp16(ks_u + (uint32_t)(row * 68 + fc4 * 4) * 4,
                     &g_kh[((size_t)bh * S + nk0 + row) * DK + fc4 * 4]);
            }
            cp_commit();
        }

        // ctx += P·V   (k = key, 8 steps; B = Vt[d][key], already tf32)
#pragma unroll
        for (int ks = 0; ks < 8; ks++) {
            const int kk = ks * 8;
            uint32_t a[2][4], b[4][2];
#pragma unroll
            for (int mf = 0; mf < 2; mf++) {
                const int row = wm + mf * 16 + g;
                a[mf][0] = Ps[row * 68 + kk + tq];
                a[mf][1] = Ps[(row + 8) * 68 + kk + tq];
                a[mf][2] = Ps[row * 68 + kk + tq + 4];
                a[mf][3] = Ps[(row + 8) * 68 + kk + tq + 4];
            }
#pragma unroll
            for (int nf = 0; nf < 4; nf++) {
                const int col = wn + nf * 8 + g;
                b[nf][0] = Vt[col * 68 + kk + tq];
                b[nf][1] = Vt[col * 68 + kk + tq + 4];
            }
#pragma unroll
            for (int mf = 0; mf < 2; mf++)
#pragma unroll
                for (int nf = 0; nf < 4; nf++)
                    mma_tf32(cacc[mf][nf], a[mf], b[nf]);
        }
        __syncthreads();       // Vt + Ps fully consumed

        // issue V(kt+1) into Vt — overlaps the next tile's QK phase
        if (kt + 1 < S / 64) {
            const int nk0 = k0 + 64;
#pragma unroll
            for (int i = 0; i < 4; i++) {
                int row = frow + i * 16;
                cp16(vt_u + (uint32_t)(row * 68 + fc4 * 4) * 4,
                     &g_vt[((size_t)bh * DK + row) * S + nk0 + fc4 * 4]);
            }
            cp_commit();
        }
    }

    // rowsum: reduce across tq lanes (same g), publish per warp-column
#pragma unroll
    for (int mf = 0; mf < 2; mf++)
#pragma unroll
        for (int hh = 0; hh < 2; hh++) {
            float v = rsum[mf][hh];
            v += __shfl_xor_sync(0xffffffffu, v, 1);
            v += __shfl_xor_sync(0xffffffffu, v, 2);
            rsum[mf][hh] = v;
        }
    if (tq == 0) {
#pragma unroll
        for (int mf = 0; mf < 2; mf++)
#pragma unroll
            for (int hh = 0; hh < 2; hh++)
                rs[(wid & 1) * 128 + wm + mf * 16 + hh * 8 + g] = rsum[mf][hh];
    }
    __syncthreads();
    if (tid < 128)
        sinv[tid] = 1.0f / (rs[tid] + rs[128 + tid]);
    __syncthreads();

    // scaled ctx -> g_ctx (tf32-rounded: consumed only by fc's MMA)
    const int b_ = bh >> 4, h_ = bh & 15;
#pragma unroll
    for (int mf = 0; mf < 2; mf++) {
        const int r0 = wm + mf * 16 + g;
        const float iv0 = sinv[r0], iv1 = sinv[r0 + 8];
#pragma unroll
        for (int nf = 0; nf < 4; nf++) {
            const int c0 = wn + nf * 8 + tq * 2;
            *(float2*)&g_ctx[((size_t)b_ * S + q0 + r0) * D + h_ * DK + c0] =
                make_float2(__uint_as_float(f2tf32(cacc[mf][nf][0] * iv0)),
                            __uint_as_float(f2tf32(cacc[mf][nf][1] * iv0)));
            *(float2*)&g_ctx[((size_t)b_ * S + q0 + r0 + 8) * D + h_ * DK + c0] =
                make_float2(__uint_as_float(f2tf32(cacc[mf][nf][2] * iv1)),
                            __uint_as_float(f2tf32(cacc[mf][nf][3] * iv1)));
        }
    }

    // ---- normalization tail: scale this CTA's own 128x2048 attn slice ----
    // All E writes above are from this CTA and ordered by __syncthreads.
    {
        float* base = attn_out + ((size_t)bh * S + q0) * S;
#pragma unroll 4
        for (int idx = tid; idx < 128 * 512; idx += 256) {
            const int row = idx >> 9;
            const int c4  = idx & 511;
            const float inv = sinv[row];
            float4* p = (float4*)(base + (size_t)row * S) + c4;
            float4 vv = *p;
            vv.x *= inv; vv.y *= inv; vv.z *= inv; vv.w *= inv;
            *p = vv;
        }
    }
}

// ---------------------------------------------------------------------------
// K5: LayerNorm over last dim (1024). One block (256 thr) per row.
// ---------------------------------------------------------------------------
__global__ __launch_bounds__(256) void ln_kernel(
    const float* __restrict__ gamma, const float* __restrict__ beta,
    float* __restrict__ out)
{
    __shared__ float s1[8], s2[8];
    __shared__ float sm_mean, sm_rstd;
    const int row = blockIdx.x;
    const int t   = threadIdx.x;
    const float* x = g_x + (size_t)row * D;

    float4 v = *(const float4*)(x + t * 4);
    float sum = v.x + v.y + v.z + v.w;
    float sq  = v.x * v.x + v.y * v.y + v.z * v.z + v.w * v.w;
#pragma unroll
    for (int m = 16; m >= 1; m >>= 1) {
        sum += __shfl_xor_sync(0xffffffffu, sum, m);
        sq  += __shfl_xor_sync(0xffffffffu, sq, m);
    }
    const int warp = t >> 5, lane = t & 31;
    if (lane == 0) { s1[warp] = sum; s2[warp] = sq; }
    __syncthreads();
    if (t == 0) {
        float a = 0.f, c = 0.f;
#pragma unroll
        for (int w = 0; w < 8; w++) { a += s1[w]; c += s2[w]; }
        float mean = a * (1.0f / D);
        float var  = c * (1.0f / D) - mean * mean;
        sm_mean = mean;
        sm_rstd = rsqrtf(var + 1e-6f);
    }
    __syncthreads();
    const float mean = sm_mean, r = sm_rstd;
    float4 g4 = *(const float4*)(gamma + t * 4);
    float4 b4 = *(const float4*)(beta + t * 4);
    float4 o;
    o.x = (v.x - mean) * r * g4.x + b4.x;
    o.y = (v.y - mean) * r * g4.y + b4.y;
    o.z = (v.z - mean) * r * g4.z + b4.z;
    o.w = (v.w - mean) * r * g4.w + b4.w;
    *(float4*)(out + (size_t)row * D + t * 4) = o;
}

// ---------------------------------------------------------------------------
extern "C" void kernel_launch(void* const* d_in, const int* in_sizes, int n_in,
                              void* d_out, int out_size)
{
    const float* q     = (const float*)d_in[0];
    const float* k     = (const float*)d_in[1];
    const float* v     = (const float*)d_in[2];
    const float* Wq    = (const float*)d_in[3];
    const float* bq    = (const float*)d_in[4];
    const float* Wfc   = (const float*)d_in[5];
    const float* bfc   = (const float*)d_in[6];
    const float* gamma = (const float*)d_in[7];
    const float* beta  = (const float*)d_in[8];

    float* out_x    = (float*)d_out;
    float* out_attn = out_x + X_ELEMS;

    cudaFuncSetAttribute(gemm_mma_kernel,
                         cudaFuncAttributeMaxDynamicSharedMemorySize, GEMM_SMEM);
    cudaFuncSetAttribute(attn_mma_kernel,
                         cudaFuncAttributeMaxDynamicSharedMemorySize, ATTN_SMEM);

    float *wqt_p, *wfct_p, *qh_p, *kh_p, *vt_p, *ctx_p, *x_p;
    cudaGetSymbolAddress((void**)&wqt_p,  g_wqt);
    cudaGetSymbolAddress((void**)&wfct_p, g_wfct);
    cudaGetSymbolAddress((void**)&qh_p,   g_qh);
    cudaGetSymbolAddress((void**)&kh_p,   g_kh);
    cudaGetSymbolAddress((void**)&vt_p,   g_vt);
    cudaGetSymbolAddress((void**)&ctx_p,  g_ctx);
    cudaGetSymbolAddress((void**)&x_p,    g_x);

    transpose_kernel<<<dim3(32, 32, 2), dim3(32, 8)>>>(Wq, Wfc);
    gemm_mma_kernel<<<dim3(8, 64, 3), 256, GEMM_SMEM>>>(
        q, k, v, wqt_p, bq, nullptr, qh_p, kh_p, vt_p, 0);
    attn_mma_kernel<<<dim3(16, 64), 256, ATTN_SMEM>>>(out_attn);
    gemm_mma_kernel<<<dim3(8, 64, 1), 256, GEMM_SMEM>>>(
        ctx_p, ctx_p, ctx_p, wfct_p, bfc, q, x_p, x_p, x_p, 1);
    ln_kernel<<<B * S, 256>>>(gamma, beta, out_x);
}

// round 9
// speedup vs baseline: 1.0509x; 1.0509x over previous
#include <cuda_runtime.h>
#include <cstdint>

// ---------------------------------------------------------------------------
// MultiHeadAttention (B=4, S=2048, D=1024, H=16, DK=64).
// Round 9: R7's 2-stage GEMM (3 CTAs/SM) restored; attention keeps the
// in-kernel scale tail and gains k-pair-interleaved smem layouts so all
// tf32 fragment loads are single LDS.64 (stride 72 words, conflict-free).
// Producers write the permuted layouts; MMA inputs are bit-identical.
// Output layout: d_out = [ x (8,388,608 f32) | attn (268,435,456 f32) ]
// ---------------------------------------------------------------------------

namespace {
constexpr int B  = 4;
constexpr int S  = 2048;
constexpr int D  = 1024;
constexpr int H  = 16;
constexpr int DK = 64;
constexpr size_t QH_ELEMS   = (size_t)B * H * S * DK;        // 8,388,608
constexpr size_t X_ELEMS    = (size_t)B * S * D;             // 8,388,608

// dense-GEMM tiling: CTA 128x128, warp 64x32 (2x4 warps), K-chunk 32,
// two cp.async stages (73,728 B -> 3 CTAs/SM).
constexpr int KC  = 32;
constexpr int NCH = D / KC;                 // 32 chunks
constexpr int GST = 36;                     // =4 mod 32 -> conflict-free .32 frags
constexpr int GTILE = 128 * GST;            // words per tile
constexpr int GEMM_SMEM = 4 * GTILE * 4;    // 73,728 B (As0,Bs0,As1,Bs1)

// attention smem layout (uint32 words), row stride 72 (=8 mod 32:
// conflict-free for paired LDS.64 fragment loads)
constexpr int AST = 72;
constexpr int AQ_OFF = 0;                   // Qs[128][72] (tf32, d-permuted)
constexpr int AK_OFF = AQ_OFF + 128 * AST;  // Ks[64][72]  (tf32, d-permuted)
constexpr int AV_OFF = AK_OFF + 64 * AST;   // Vt[64][72]  (tf32; d rows, key cols s-permuted)
constexpr int AP_OFF = AV_OFF + 64 * AST;   // Ps[128][72] (tf32, key-permuted)
constexpr int ARS_OFF = AP_OFF + 128 * AST; // rs[2][128] floats
constexpr int AIV_OFF = ARS_OFF + 256;      // sinv[128] floats
constexpr int ATTN_SMEM = (AIV_OFF + 128) * 4;   // 112,128 B (2 CTAs/SM)
}

// Scratch (allocation-free rule: __device__ globals)
__device__ float g_qh[QH_ELEMS];           // tf32-valued, d-dim 8-group permuted
__device__ float g_kh[QH_ELEMS];           // tf32-valued, d-dim 8-group permuted
__device__ float g_vt[QH_ELEMS];           // tf32-valued; [bh][d][s], s 8-group permuted
__device__ float g_ctx[X_ELEMS];           // tf32-valued (natural layout)
__device__ float g_x[X_ELEMS];             // fp32
__device__ float g_wqt[(size_t)D * D];     // Wq^T  [N][K], tf32-valued
__device__ float g_wfct[(size_t)D * D];    // Wfc^T [N][K], tf32-valued

// ---------------------------------------------------------------------------
// helpers
// ---------------------------------------------------------------------------
__device__ __forceinline__ uint32_t smem_to_u32(const void* p) {
    uint32_t a;
    asm("{ .reg .u64 t; cvta.to.shared.u64 t, %1; cvt.u32.u64 %0, t; }"
        : "=r"(a) : "l"(p));
    return a;
}
__device__ __forceinline__ uint32_t f2tf32(float x) {
    uint32_t r;
    asm("cvt.rna.tf32.f32 %0, %1;" : "=r"(r) : "f"(x));
    return r;
}
__device__ __forceinline__ uint32_t tf32b(uint32_t rawbits) {
    return f2tf32(__uint_as_float(rawbits));
}
__device__ __forceinline__ void mma_tf32(float* d, const uint32_t* a, const uint32_t* b) {
    asm volatile(
        "mma.sync.aligned.m16n8k8.row.col.f32.tf32.tf32.f32 "
        "{%0,%1,%2,%3}, {%4,%5,%6,%7}, {%8,%9}, {%0,%1,%2,%3};"
        : "+f"(d[0]), "+f"(d[1]), "+f"(d[2]), "+f"(d[3])
        : "r"(a[0]), "r"(a[1]), "r"(a[2]), "r"(a[3]), "r"(b[0]), "r"(b[1]));
}
__device__ __forceinline__ void cp16(uint32_t dst, const void* src) {
    asm volatile("cp.async.cg.shared.global [%0], [%1], 16;" :: "r"(dst), "l"(src));
}
__device__ __forceinline__ void cp8(uint32_t dst, const void* src) {
    asm volatile("cp.async.ca.shared.global [%0], [%1], 8;" :: "r"(dst), "l"(src));
}
__device__ __forceinline__ void cp_commit() {
    asm volatile("cp.async.commit_group;" ::: "memory");
}
__device__ __forceinline__ void cp_wait0() {
    asm volatile("cp.async.wait_group 0;" ::: "memory");
}
__device__ __forceinline__ void cp_wait1() {
    asm volatile("cp.async.wait_group 1;" ::: "memory");
}
// exp via FMA pipe: magic-number range reduction + deg-5 poly (rel err ~2e-6).
__device__ __forceinline__ float fast_exp(float x) {
    const float L2E = 1.4426950408889634f;
    float t = fmaf(x, L2E, 12582912.0f);
    float n = t - 12582912.0f;
    float f = fmaf(x, L2E, -n);
    float p = 0.0013333558f;
    p = fmaf(p, f, 0.0096181291f);
    p = fmaf(p, f, 0.0555041087f);
    p = fmaf(p, f, 0.2402265069f);
    p = fmaf(p, f, 0.6931471806f);
    p = fmaf(p, f, 1.0f);
    return __int_as_float(__float_as_int(p) + (__float_as_int(t) << 23));
}

// ---------------------------------------------------------------------------
// K0: transpose Wq and Wfc once -> g_wqt / g_wfct (tf32-rounded at store)
// ---------------------------------------------------------------------------
__global__ __launch_bounds__(256) void transpose_kernel(
    const float* __restrict__ Wq, const float* __restrict__ Wfc)
{
    __shared__ float tile[32][33];
    const float* src = blockIdx.z ? Wfc : Wq;
    float*       dst = blockIdx.z ? g_wfct : g_wqt;
    int x = blockIdx.x * 32 + threadIdx.x;
    int y = blockIdx.y * 32 + threadIdx.y;
#pragma unroll
    for (int i = 0; i < 32; i += 8)
        tile[threadIdx.y + i][threadIdx.x] = src[(size_t)(y + i) * D + x];
    __syncthreads();
    int tx = blockIdx.y * 32 + threadIdx.x;
    int ty = blockIdx.x * 32 + threadIdx.y;
#pragma unroll
    for (int i = 0; i < 32; i += 8)
        dst[(size_t)(ty + i) * D + tx] =
            __uint_as_float(f2tf32(tile[threadIdx.x][threadIdx.y + i]));
}

// ---------------------------------------------------------------------------
// K1/K4: tf32 mma.sync GEMM, 2-stage cp.async pipeline (R7-proven).
// Y[m,n] = A[m,:] . Bt[n,:]  (+bias[, +resid])
// mode 0: proj; z=0,1 -> qh/kh with d-dim 8-group PERMUTED positions;
//         z=2 -> V transposed to g_vt with s 8-group PERMUTED positions.
//         A raw fp32 (cvt at fragment load); outputs tf32-rounded.
// mode 1: fc. A (g_ctx) and B pre-rounded -> no cvts; output fp32 + resid.
// ---------------------------------------------------------------------------
__global__ __launch_bounds__(256) void gemm_mma_kernel(
    const float* __restrict__ A0, const float* __restrict__ A1,
    const float* __restrict__ A2, const float* __restrict__ Bt,
    const float* __restrict__ bias, const float* __restrict__ resid,
    float* __restrict__ O0, float* __restrict__ O1, float* __restrict__ O2,
    int mode)
{
    extern __shared__ uint32_t smu[];
    const uint32_t smem_u = smem_to_u32(smu);

    const int tid  = threadIdx.x;
    const int wid  = tid >> 5, lane = tid & 31;
    const int g    = lane >> 2, tq = lane & 3;
    const int wm   = (wid >> 2) * 64;
    const int wn   = (wid & 3) * 32;
    const int n0   = blockIdx.x * 128;
    const int m0   = blockIdx.y * 128;

    const float* Ap;
    float* Op;
    if (blockIdx.z == 0)      { Ap = A0; Op = O0; }
    else if (blockIdx.z == 1) { Ap = A1; Op = O1; }
    else                      { Ap = A2; Op = O2; }

    float acc[4][4][4];
#pragma unroll
    for (int i = 0; i < 4; i++)
#pragma unroll
        for (int j = 0; j < 4; j++)
#pragma unroll
            for (int r = 0; r < 4; r++) acc[i][j][r] = 0.f;

    // prologue: issue chunks 0 (stage 0) and 1 (stage 1)
#pragma unroll
    for (int c0 = 0; c0 < 2; c0++) {
        const int kt = c0 * KC;
        const uint32_t sbase = smem_u + (uint32_t)(c0 * 2 * GTILE) * 4;
#pragma unroll
        for (int j = 0; j < 8; j++) {
            int idx = tid + j * 256;          // 2048 8B-chunks per tile
            int row = idx >> 4, ch = idx & 15;
            uint32_t off = (uint32_t)(row * GST + ch * 2) * 4;
            cp8(sbase + off,             Ap + (size_t)(m0 + row) * D + kt + ch * 2);
            cp8(sbase + off + GTILE * 4, Bt + (size_t)(n0 + row) * D + kt + ch * 2);
        }
        cp_commit();
    }

    for (int c = 0; c < NCH; c++) {
        const int st = c & 1;
        if (c + 1 < NCH) cp_wait1(); else cp_wait0();
        __syncthreads();

        const uint32_t* As = smu + st * 2 * GTILE;
        const uint32_t* Bs = As + GTILE;

#pragma unroll
        for (int ks = 0; ks < KC / 8; ks++) {
            const int kk = ks * 8;
            uint32_t a[4][4], b[4][2];
            if (mode == 0) {
#pragma unroll
                for (int mf = 0; mf < 4; mf++) {
                    const int row = wm + mf * 16 + g;
                    a[mf][0] = tf32b(As[row * GST + kk + tq]);
                    a[mf][1] = tf32b(As[(row + 8) * GST + kk + tq]);
                    a[mf][2] = tf32b(As[row * GST + kk + tq + 4]);
                    a[mf][3] = tf32b(As[(row + 8) * GST + kk + tq + 4]);
                }
            } else {
#pragma unroll
                for (int mf = 0; mf < 4; mf++) {
                    const int row = wm + mf * 16 + g;
                    a[mf][0] = As[row * GST + kk + tq];
                    a[mf][1] = As[(row + 8) * GST + kk + tq];
                    a[mf][2] = As[row * GST + kk + tq + 4];
                    a[mf][3] = As[(row + 8) * GST + kk + tq + 4];
                }
            }
#pragma unroll
            for (int nf = 0; nf < 4; nf++) {
                const int col = wn + nf * 8 + g;
                b[nf][0] = Bs[col * GST + kk + tq];
                b[nf][1] = Bs[col * GST + kk + tq + 4];
            }
#pragma unroll
            for (int mf = 0; mf < 4; mf++)
#pragma unroll
                for (int nf = 0; nf < 4; nf++)
                    mma_tf32(acc[mf][nf], a[mf], b[nf]);
        }
        __syncthreads();

        // refill this stage with chunk c+2 (overlaps chunk c+1's compute)
        if (c + 2 < NCH) {
            const int kt = (c + 2) * KC;
            const uint32_t sbase = smem_u + (uint32_t)(st * 2 * GTILE) * 4;
#pragma unroll
            for (int j = 0; j < 8; j++) {
                int idx = tid + j * 256;
                int row = idx >> 4, ch = idx & 15;
                uint32_t off = (uint32_t)(row * GST + ch * 2) * 4;
                cp8(sbase + off,             Ap + (size_t)(m0 + row) * D + kt + ch * 2);
                cp8(sbase + off + GTILE * 4, Bt + (size_t)(n0 + row) * D + kt + ch * 2);
            }
            cp_commit();
        }
    }

    // within-8 k-pair permutation positions for this thread's (even, odd) cols
    const int p0 = (tq < 2) ? 4 * tq     : 4 * tq - 7;   // pos of natural col 2tq
    const int p1 = (tq < 2) ? 4 * tq + 2 : 4 * tq - 5;   // pos of natural col 2tq+1

#pragma unroll
    for (int mf = 0; mf < 4; mf++) {
#pragma unroll
        for (int nf = 0; nf < 4; nf++) {
            const int m = m0 + wm + mf * 16 + g;
            const int n = n0 + wn + nf * 8 + tq * 2;
            float bx = bias[n], by = bias[n + 1];
#pragma unroll
            for (int half = 0; half < 2; half++) {
                const int mm = m + half * 8;
                float vx = acc[mf][nf][half * 2 + 0] + bx;
                float vy = acc[mf][nf][half * 2 + 1] + by;
                if (mode == 0) {
                    // outputs feed MMA only -> tf32-round at producer
                    vx = __uint_as_float(f2tf32(vx));
                    vy = __uint_as_float(f2tf32(vy));
                    const int h = n >> 6, dk = n & 63;
                    const int bb_ = mm >> 11, s = mm & 2047;
                    if (blockIdx.z == 2) {
                        // V transposed [bh][d][s], s permuted within 8-group
                        const int s8 = mm & 7;   // == g
                        const int sp = (mm & ~7) |
                                       ((s8 < 4) ? 2 * s8 : 2 * (s8 - 4) + 1);
                        const int spl = sp & 2047;
                        float* vtb = &g_vt[(((size_t)bb_ * H + h) * DK + dk) * S + spl];
                        vtb[0] = vx;
                        vtb[S] = vy;
                    } else {
                        // qh/kh: d-dim permuted within its 8-group
                        const int dkb = dk & ~7;
                        float* orow = &O0[0];  // placate compiler; real ptr below
                        orow = Op + (((size_t)bb_ * H + h) * S + s) * DK;
                        orow[dkb + p0] = vx;
                        orow[dkb + p1] = vy;
                    }
                } else {
                    const float* rr = resid + (size_t)mm * D + n;
                    float2 r2 = *(const float2*)rr;
                    float2* p = (float2*)&Op[(size_t)mm * D + n];
                    *p = make_float2(vx + r2.x, vy + r2.y);
                }
            }
        }
    }
}

// ---------------------------------------------------------------------------
// K2: attention via tf32 mma.sync; k-pair-interleaved smem (all fragment
// loads LDS.64, stride 72 conflict-free); cp.async K/V slid into dead
// phases; in-kernel normalization tail for this CTA's attn slice.
// grid (16 q-tiles, 64 bh), block 256. Warp grid 4x2.
// ---------------------------------------------------------------------------
__global__ __launch_bounds__(256, 2) void attn_mma_kernel(float* __restrict__ attn_out)
{
    extern __shared__ uint32_t smu[];
    uint32_t* Qs = smu + AQ_OFF;
    uint32_t* Ks = smu + AK_OFF;
    uint32_t* Vt = smu + AV_OFF;
    uint32_t* Ps = smu + AP_OFF;
    float* rs    = (float*)(smu + ARS_OFF);
    float* sinv  = (float*)(smu + AIV_OFF);
    const uint32_t smem_u = smem_to_u32(smu);
    const uint32_t ks_u = smem_u + AK_OFF * 4;
    const uint32_t vt_u = smem_u + AV_OFF * 4;

    const int bh = blockIdx.y;
    const int q0 = blockIdx.x * 128;
    const int tid = threadIdx.x;
    const int wid = tid >> 5, lane = tid & 31;
    const int g = lane >> 2, tq = lane & 3;
    const int wm = (wid >> 1) * 32;
    const int wn = (wid & 1) * 32;
    const float scale = 0.125f;
    const int tq2 = 2 * tq;

    const int frow = tid >> 4, fc4 = tid & 15;     // K/V fill: rows frow + i*16

    // Q tile: g_qh is tf32-valued & d-permuted; identity copy (STS.128)
#pragma unroll
    for (int i = 0; i < 8; i++) {
        int f4 = tid + i * 256;
        int row = f4 >> 4, c4 = f4 & 15;
        float4 qv = *(const float4*)&g_qh[((size_t)bh * S + q0 + row) * DK + c4 * 4];
        uint32_t* qd = &Qs[row * AST + c4 * 4];
        uint4 qb;
        qb.x = __float_as_uint(qv.x * scale);
        qb.y = __float_as_uint(qv.y * scale);
        qb.z = __float_as_uint(qv.z * scale);
        qb.w = __float_as_uint(qv.w * scale);
        *(uint4*)qd = qb;
    }

    // prologue: issue K(0) then V(0) as separate groups (identity copies of
    // permuted gmem layouts)
#pragma unroll
    for (int i = 0; i < 4; i++) {
        int row = frow + i * 16;
        cp16(ks_u + (uint32_t)(row * AST + fc4 * 4) * 4,
             &g_kh[((size_t)bh * S + row) * DK + fc4 * 4]);
    }
    cp_commit();
#pragma unroll
    for (int i = 0; i < 4; i++) {
        int row = frow + i * 16;
        cp16(vt_u + (uint32_t)(row * AST + fc4 * 4) * 4,
             &g_vt[((size_t)bh * DK + row) * S + fc4 * 4]);
    }
    cp_commit();

    float cacc[2][4][4];
    float rsum[2][2] = {{0.f, 0.f}, {0.f, 0.f}};
#pragma unroll
    for (int mf = 0; mf < 2; mf++)
#pragma unroll
        for (int nf = 0; nf < 4; nf++)
#pragma unroll
            for (int r = 0; r < 4; r++) cacc[mf][nf][r] = 0.f;

    // Ps store positions (within-8 permutation of this thread's cols)
    const int pp0 = (tq < 2) ? 4 * tq     : 4 * tq - 7;
    const int pp1 = (tq < 2) ? 4 * tq + 2 : 4 * tq - 5;

    for (int kt = 0; kt < S / 64; kt++) {
        const int k0 = kt * 64;

        cp_wait1();            // K(kt) arrived (V(kt) may still be in flight)
        __syncthreads();

        // S = Q·K^T  (k = d, 8 steps); paired LDS.64 fragment loads
        float sacc[2][4][4];
#pragma unroll
        for (int mf = 0; mf < 2; mf++)
#pragma unroll
            for (int nf = 0; nf < 4; nf++)
#pragma unroll
                for (int r = 0; r < 4; r++) sacc[mf][nf][r] = 0.f;
#pragma unroll
        for (int ks = 0; ks < 8; ks++) {
            const int kk = ks * 8;
            uint32_t a[2][4], b[4][2];
#pragma unroll
            for (int mf = 0; mf < 2; mf++) {
                const int row = wm + mf * 16 + g;
                uint2 a0 = *(const uint2*)&Qs[row * AST + kk + tq2];
                uint2 a1 = *(const uint2*)&Qs[(row + 8) * AST + kk + tq2];
                a[mf][0] = a0.x; a[mf][2] = a0.y;
                a[mf][1] = a1.x; a[mf][3] = a1.y;
            }
#pragma unroll
            for (int nf = 0; nf < 4; nf++) {
                const int col = wn + nf * 8 + g;
                uint2 bb = *(const uint2*)&Ks[col * AST + kk + tq2];
                b[nf][0] = bb.x; b[nf][1] = bb.y;
            }
#pragma unroll
            for (int mf = 0; mf < 2; mf++)
#pragma unroll
                for (int nf = 0; nf < 4; nf++)
                    mma_tf32(sacc[mf][nf], a[mf], b[nf]);
        }

        // exp, rowsum, E -> gmem (unnormalized, NATURAL col order),
        // P -> smem (tf32, key-permuted positions)
#pragma unroll
        for (int mf = 0; mf < 2; mf++) {
            const int r0 = wm + mf * 16 + g;
#pragma unroll
            for (int nf = 0; nf < 4; nf++) {
                const int c0 = wn + nf * 8 + tq2;
                const int cb = wn + nf * 8;
                float e00 = fast_exp(sacc[mf][nf][0]);
                float e01 = fast_exp(sacc[mf][nf][1]);
                float e10 = fast_exp(sacc[mf][nf][2]);
                float e11 = fast_exp(sacc[mf][nf][3]);
                rsum[mf][0] += e00 + e01;
                rsum[mf][1] += e10 + e11;
                *(float2*)&attn_out[((size_t)bh * S + q0 + r0) * S + k0 + c0] =
                    make_float2(e00, e01);
                *(float2*)&attn_out[((size_t)bh * S + q0 + r0 + 8) * S + k0 + c0] =
                    make_float2(e10, e11);
                Ps[r0 * AST + cb + pp0]       = f2tf32(e00);
                Ps[r0 * AST + cb + pp1]       = f2tf32(e01);
                Ps[(r0 + 8) * AST + cb + pp0] = f2tf32(e10);
                Ps[(r0 + 8) * AST + cb + pp1] = f2tf32(e11);
            }
        }

        cp_wait0();            // V(kt) arrived
        __syncthreads();       // publish V + Ps; Ks fully consumed

        // issue K(kt+1) into Ks — overlaps the P·V phase below
        if (kt + 1 < S / 64) {
            const int nk0 = k0 + 64;
#pragma unroll
            for (int i = 0; i < 4; i++) {
                int row = frow + i * 16;
                cp16(ks_u + (uint32_t)(row * AST + fc4 * 4) * 4,
                     &g_kh[((size_t)bh * S + nk0 + row) * DK + fc4 * 4]);
            }
            cp_commit();
        }

        // ctx += P·V  (k = keys, permuted pairs; LDS.64 frags)
#pragma unroll
        for (int ks = 0; ks < 8; ks++) {
            const int kk = ks * 8;
            uint32_t a[2][4], b[4][2];
#pragma unroll
            for (int mf = 0; mf < 2; mf++) {
                const int row = wm + mf * 16 + g;
                uint2 a0 = *(const uint2*)&Ps[row * AST + kk + tq2];
                uint2 a1 = *(const uint2*)&Ps[(row + 8) * AST + kk + tq2];
                a[mf][0] = a0.x; a[mf][2] = a0.y;
                a[mf][1] = a1.x; a[mf][3] = a1.y;
            }
#pragma unroll
            for (int nf = 0; nf < 4; nf++) {
                const int col = wn + nf * 8 + g;
                uint2 bb = *(const uint2*)&Vt[col * AST + kk + tq2];
                b[nf][0] = bb.x; b[nf][1] = bb.y;
            }
#pragma unroll
            for (int mf = 0; mf < 2; mf++)
#pragma unroll
                for (int nf = 0; nf < 4; nf++)
                    mma_tf32(cacc[mf][nf], a[mf], b[nf]);
        }
        __syncthreads();       // Vt + Ps fully consumed

        // issue V(kt+1) into Vt — overlaps the next tile's QK phase
        if (kt + 1 < S / 64) {
            const int nk0 = k0 + 64;
#pragma unroll
            for (int i = 0; i < 4; i++) {
                int row = frow + i * 16;
                cp16(vt_u + (uint32_t)(row * AST + fc4 * 4) * 4,
                     &g_vt[((size_t)bh * DK + row) * S + nk0 + fc4 * 4]);
            }
            cp_commit();
        }
    }

    // rowsum: reduce across tq lanes (same g), publish per warp-column
#pragma unroll
    for (int mf = 0; mf < 2; mf++)
#pragma unroll
        for (int hh = 0; hh < 2; hh++) {
            float v = rsum[mf][hh];
            v += __shfl_xor_sync(0xffffffffu, v, 1);
            v += __shfl_xor_sync(0xffffffffu, v, 2);
            rsum[mf][hh] = v;
        }
    if (tq == 0) {
#pragma unroll
        for (int mf = 0; mf < 2; mf++)
#pragma unroll
            for (int hh = 0; hh < 2; hh++)
                rs[(wid & 1) * 128 + wm + mf * 16 + hh * 8 + g] = rsum[mf][hh];
    }
    __syncthreads();
    if (tid < 128)
        sinv[tid] = 1.0f / (rs[tid] + rs[128 + tid]);
    __syncthreads();

    // scaled ctx -> g_ctx (NATURAL layout; tf32-rounded for fc's MMA)
    const int b_ = bh >> 4, h_ = bh & 15;
#pragma unroll
    for (int mf = 0; mf < 2; mf++) {
        const int r0 = wm + mf * 16 + g;
        const float iv0 = sinv[r0], iv1 = sinv[r0 + 8];
#pragma unroll
        for (int nf = 0; nf < 4; nf++) {
            const int c0 = wn + nf * 8 + tq2;
            *(float2*)&g_ctx[((size_t)b_ * S + q0 + r0) * D + h_ * DK + c0] =
                make_float2(__uint_as_float(f2tf32(cacc[mf][nf][0] * iv0)),
                            __uint_as_float(f2tf32(cacc[mf][nf][1] * iv0)));
            *(float2*)&g_ctx[((size_t)b_ * S + q0 + r0 + 8) * D + h_ * DK + c0] =
                make_float2(__uint_as_float(f2tf32(cacc[mf][nf][2] * iv1)),
                            __uint_as_float(f2tf32(cacc[mf][nf][3] * iv1)));
        }
    }

    // ---- normalization tail: scale this CTA's own 128x2048 attn slice ----
    {
        float* base = attn_out + ((size_t)bh * S + q0) * S;
#pragma unroll 4
        for (int idx = tid; idx < 128 * 512; idx += 256) {
            const int row = idx >> 9;
            const int c4  = idx & 511;
            const float inv = sinv[row];
            float4* p = (float4*)(base + (size_t)row * S) + c4;
            float4 vv = __ldcs(p);
            vv.x *= inv; vv.y *= inv; vv.z *= inv; vv.w *= inv;
            __stcs(p, vv);
        }
    }
}

// ---------------------------------------------------------------------------
// K5: LayerNorm over last dim (1024). One block (256 thr) per row.
// ---------------------------------------------------------------------------
__global__ __launch_bounds__(256) void ln_kernel(
    const float* __restrict__ gamma, const float* __restrict__ beta,
    float* __restrict__ out)
{
    __shared__ float s1[8], s2[8];
    __shared__ float sm_mean, sm_rstd;
    const int row = blockIdx.x;
    const int t   = threadIdx.x;
    const float* x = g_x + (size_t)row * D;

    float4 v = *(const float4*)(x + t * 4);
    float sum = v.x + v.y + v.z + v.w;
    float sq  = v.x * v.x + v.y * v.y + v.z * v.z + v.w * v.w;
#pragma unroll
    for (int m = 16; m >= 1; m >>= 1) {
        sum += __shfl_xor_sync(0xffffffffu, sum, m);
        sq  += __shfl_xor_sync(0xffffffffu, sq, m);
    }
    const int warp = t >> 5, lane = t & 31;
    if (lane == 0) { s1[warp] = sum; s2[warp] = sq; }
    __syncthreads();
    if (t == 0) {
        float a = 0.f, c = 0.f;
#pragma unroll
        for (int w = 0; w < 8; w++) { a += s1[w]; c += s2[w]; }
        float mean = a * (1.0f / D);
        float var  = c * (1.0f / D) - mean * mean;
        sm_mean = mean;
        sm_rstd = rsqrtf(var + 1e-6f);
    }
    __syncthreads();
    const float mean = sm_mean, r = sm_rstd;
    float4 g4 = *(const float4*)(gamma + t * 4);
    float4 b4 = *(const float4*)(beta + t * 4);
    float4 o;
    o.x = (v.x - mean) * r * g4.x + b4.x;
    o.y = (v.y - mean) * r * g4.y + b4.y;
    o.z = (v.z - mean) * r * g4.z + b4.z;
    o.w = (v.w - mean) * r * g4.w + b4.w;
    *(float4*)(out + (size_t)row * D + t * 4) = o;
}

// ---------------------------------------------------------------------------
extern "C" void kernel_launch(void* const* d_in, const int* in_sizes, int n_in,
                              void* d_out, int out_size)
{
    const float* q     = (const float*)d_in[0];
    const float* k     = (const float*)d_in[1];
    const float* v     = (const float*)d_in[2];
    const float* Wq    = (const float*)d_in[3];
    const float* bq    = (const float*)d_in[4];
    const float* Wfc   = (const float*)d_in[5];
    const float* bfc   = (const float*)d_in[6];
    const float* gamma = (const float*)d_in[7];
    const float* beta  = (const float*)d_in[8];

    float* out_x    = (float*)d_out;
    float* out_attn = out_x + X_ELEMS;

    cudaFuncSetAttribute(gemm_mma_kernel,
                         cudaFuncAttributeMaxDynamicSharedMemorySize, GEMM_SMEM);
    cudaFuncSetAttribute(attn_mma_kernel,
                         cudaFuncAttributeMaxDynamicSharedMemorySize, ATTN_SMEM);

    float *wqt_p, *wfct_p, *qh_p, *kh_p, *vt_p, *ctx_p, *x_p;
    cudaGetSymbolAddress((void**)&wqt_p,  g_wqt);
    cudaGetSymbolAddress((void**)&wfct_p, g_wfct);
    cudaGetSymbolAddress((void**)&qh_p,   g_qh);
    cudaGetSymbolAddress((void**)&kh_p,   g_kh);
    cudaGetSymbolAddress((void**)&vt_p,   g_vt);
    cudaGetSymbolAddress((void**)&ctx_p,  g_ctx);
    cudaGetSymbolAddress((void**)&x_p,    g_x);

    transpose_kernel<<<dim3(32, 32, 2), dim3(32, 8)>>>(Wq, Wfc);
    gemm_mma_kernel<<<dim3(8, 64, 3), 256, GEMM_SMEM>>>(
        q, k, v, wqt_p, bq, nullptr, qh_p, kh_p, vt_p, 0);
    attn_mma_kernel<<<dim3(16, 64), 256, ATTN_SMEM>>>(out_attn);
    gemm_mma_kernel<<<dim3(8, 64, 1), 256, GEMM_SMEM>>>(
        ctx_p, ctx_p, ctx_p, wfct_p, bfc, q, x_p, x_p, x_p, 1);
    ln_kernel<<<B * S, 256>>>(gamma, beta, out_x);
}

// round 11
// speedup vs baseline: 1.3334x; 1.2688x over previous
#include <cuda_runtime.h>
#include <cuda_fp16.h>
#include <cstdint>

// ---------------------------------------------------------------------------
// MultiHeadAttention (B=4, S=2048, D=1024, H=16, DK=64).
// Round 11: R10 (fp16 m16n8k16 attention) with the compile fix
// (half2 -> u32 bit-cast). Dense GEMMs stay tf32 (R7-proven 2-stage
// cp.async). qh pre-scaled by 1/8 at projection. Separate attn_scale.
// Output layout: d_out = [ x (8,388,608 f32) | attn (268,435,456 f32) ]
// ---------------------------------------------------------------------------

namespace {
constexpr int B  = 4;
constexpr int S  = 2048;
constexpr int D  = 1024;
constexpr int H  = 16;
constexpr int DK = 64;
constexpr size_t QH_ELEMS   = (size_t)B * H * S * DK;        // 8,388,608
constexpr size_t X_ELEMS    = (size_t)B * S * D;             // 8,388,608
constexpr size_t ATTN_ELEMS = (size_t)B * H * S * (size_t)S; // 268,435,456

// dense-GEMM tiling: CTA 128x128, warp 64x32 (2x4 warps), K-chunk 32,
// two cp.async stages (R7-proven).
constexpr int KC  = 32;
constexpr int NCH = D / KC;                 // 32 chunks
constexpr int GST = 36;                     // =4 mod 32 -> conflict-free frags
constexpr int GTILE = 128 * GST;            // words per tile
constexpr int GEMM_SMEM = 4 * GTILE * 4;    // 73,728 B

// attention smem (32-bit words). Rows hold 64 fp16 (32 words) + 4 pad words.
// stride 36 = 4 mod 32 -> LDS.32 fragment loads conflict-free.
constexpr int AST = 36;
constexpr int AQ_OFF = 0;                   // Qs[128][36w] fp16, pre-scaled
constexpr int AK_OFF = AQ_OFF + 128 * AST;  // Ks[64][36w]  fp16
constexpr int AV_OFF = AK_OFF + 64 * AST;   // Vt[64][36w]  fp16 (d rows, key cols)
constexpr int AP_OFF = AV_OFF + 64 * AST;   // Ps[128][36w] fp16
constexpr int ARS_OFF = AP_OFF + 128 * AST; // rs[2][128] floats
constexpr int AIV_OFF = ARS_OFF + 256;      // sinv[128] floats
constexpr int ATTN_SMEM = (AIV_OFF + 128) * 4;   // 56,832 B
}

// Scratch (allocation-free rule: __device__ globals)
__device__ __half g_qh[QH_ELEMS];          // fp16, pre-scaled by 0.125
__device__ __half g_kh[QH_ELEMS];          // fp16
__device__ __half g_vt[QH_ELEMS];          // fp16; V transposed [bh][d][s]
__device__ float  g_ctx[X_ELEMS];          // tf32-valued
__device__ float  g_x[X_ELEMS];            // fp32
__device__ float  g_rinv[(size_t)B * H * S];
__device__ float  g_wqt[(size_t)D * D];    // Wq^T  [N][K], tf32-valued
__device__ float  g_wfct[(size_t)D * D];   // Wfc^T [N][K], tf32-valued

// ---------------------------------------------------------------------------
// helpers
// ---------------------------------------------------------------------------
__device__ __forceinline__ uint32_t smem_to_u32(const void* p) {
    uint32_t a;
    asm("{ .reg .u64 t; cvta.to.shared.u64 t, %1; cvt.u32.u64 %0, t; }"
        : "=r"(a) : "l"(p));
    return a;
}
__device__ __forceinline__ uint32_t f2tf32(float x) {
    uint32_t r;
    asm("cvt.rna.tf32.f32 %0, %1;" : "=r"(r) : "f"(x));
    return r;
}
__device__ __forceinline__ uint32_t tf32b(uint32_t rawbits) {
    return f2tf32(__uint_as_float(rawbits));
}
__device__ __forceinline__ uint32_t h2u(__half2 h) {
    uint32_t u;
    __builtin_memcpy(&u, &h, 4);
    return u;
}
__device__ __forceinline__ void mma_tf32(float* d, const uint32_t* a, const uint32_t* b) {
    asm volatile(
        "mma.sync.aligned.m16n8k8.row.col.f32.tf32.tf32.f32 "
        "{%0,%1,%2,%3}, {%4,%5,%6,%7}, {%8,%9}, {%0,%1,%2,%3};"
        : "+f"(d[0]), "+f"(d[1]), "+f"(d[2]), "+f"(d[3])
        : "r"(a[0]), "r"(a[1]), "r"(a[2]), "r"(a[3]), "r"(b[0]), "r"(b[1]));
}
__device__ __forceinline__ void mma_f16(float* d, const uint32_t* a, const uint32_t* b) {
    asm volatile(
        "mma.sync.aligned.m16n8k16.row.col.f32.f16.f16.f32 "
        "{%0,%1,%2,%3}, {%4,%5,%6,%7}, {%8,%9}, {%0,%1,%2,%3};"
        : "+f"(d[0]), "+f"(d[1]), "+f"(d[2]), "+f"(d[3])
        : "r"(a[0]), "r"(a[1]), "r"(a[2]), "r"(a[3]), "r"(b[0]), "r"(b[1]));
}
__device__ __forceinline__ void cp16(uint32_t dst, const void* src) {
    asm volatile("cp.async.cg.shared.global [%0], [%1], 16;" :: "r"(dst), "l"(src));
}
__device__ __forceinline__ void cp8(uint32_t dst, const void* src) {
    asm volatile("cp.async.ca.shared.global [%0], [%1], 8;" :: "r"(dst), "l"(src));
}
__device__ __forceinline__ void cp_commit() {
    asm volatile("cp.async.commit_group;" ::: "memory");
}
__device__ __forceinline__ void cp_wait0() {
    asm volatile("cp.async.wait_group 0;" ::: "memory");
}
__device__ __forceinline__ void cp_wait1() {
    asm volatile("cp.async.wait_group 1;" ::: "memory");
}
// exp via FMA pipe: magic-number range reduction + deg-5 poly (rel err ~2e-6).
__device__ __forceinline__ float fast_exp(float x) {
    const float L2E = 1.4426950408889634f;
    float t = fmaf(x, L2E, 12582912.0f);
    float n = t - 12582912.0f;
    float f = fmaf(x, L2E, -n);
    float p = 0.0013333558f;
    p = fmaf(p, f, 0.0096181291f);
    p = fmaf(p, f, 0.0555041087f);
    p = fmaf(p, f, 0.2402265069f);
    p = fmaf(p, f, 0.6931471806f);
    p = fmaf(p, f, 1.0f);
    return __int_as_float(__float_as_int(p) + (__float_as_int(t) << 23));
}

// ---------------------------------------------------------------------------
// K0: transpose Wq and Wfc once -> g_wqt / g_wfct (tf32-rounded at store)
// ---------------------------------------------------------------------------
__global__ __launch_bounds__(256) void transpose_kernel(
    const float* __restrict__ Wq, const float* __restrict__ Wfc)
{
    __shared__ float tile[32][33];
    const float* src = blockIdx.z ? Wfc : Wq;
    float*       dst = blockIdx.z ? g_wfct : g_wqt;
    int x = blockIdx.x * 32 + threadIdx.x;
    int y = blockIdx.y * 32 + threadIdx.y;
#pragma unroll
    for (int i = 0; i < 32; i += 8)
        tile[threadIdx.y + i][threadIdx.x] = src[(size_t)(y + i) * D + x];
    __syncthreads();
    int tx = blockIdx.y * 32 + threadIdx.x;
    int ty = blockIdx.x * 32 + threadIdx.y;
#pragma unroll
    for (int i = 0; i < 32; i += 8)
        dst[(size_t)(ty + i) * D + tx] =
            __uint_as_float(f2tf32(tile[threadIdx.x][threadIdx.y + i]));
}

// ---------------------------------------------------------------------------
// K1/K4: tf32 mma.sync GEMM, 2-stage cp.async pipeline (R7-proven).
// Y[m,n] = A[m,:] . Bt[n,:]  (+bias[, +resid])
// mode 0: proj -> fp16 outputs. z=0 qh (scaled by 0.125), z=1 kh,
//         z=2 V transposed to g_vt. A raw fp32 (cvt at fragment load).
// mode 1: fc. A (g_ctx) and B pre-rounded tf32; output fp32 + resid.
// ---------------------------------------------------------------------------
__global__ __launch_bounds__(256) void gemm_mma_kernel(
    const float* __restrict__ A0, const float* __restrict__ A1,
    const float* __restrict__ A2, const float* __restrict__ Bt,
    const float* __restrict__ bias, const float* __restrict__ resid,
    float* __restrict__ O1f, int mode)
{
    extern __shared__ uint32_t smu[];
    const uint32_t smem_u = smem_to_u32(smu);

    const int tid  = threadIdx.x;
    const int wid  = tid >> 5, lane = tid & 31;
    const int g    = lane >> 2, tq = lane & 3;
    const int wm   = (wid >> 2) * 64;
    const int wn   = (wid & 3) * 32;
    const int n0   = blockIdx.x * 128;
    const int m0   = blockIdx.y * 128;

    const float* Ap;
    if (blockIdx.z == 0)      Ap = A0;
    else if (blockIdx.z == 1) Ap = A1;
    else                      Ap = A2;

    float acc[4][4][4];
#pragma unroll
    for (int i = 0; i < 4; i++)
#pragma unroll
        for (int j = 0; j < 4; j++)
#pragma unroll
            for (int r = 0; r < 4; r++) acc[i][j][r] = 0.f;

    // prologue: issue chunks 0 (stage 0) and 1 (stage 1)
#pragma unroll
    for (int c0 = 0; c0 < 2; c0++) {
        const int kt = c0 * KC;
        const uint32_t sbase = smem_u + (uint32_t)(c0 * 2 * GTILE) * 4;
#pragma unroll
        for (int j = 0; j < 8; j++) {
            int idx = tid + j * 256;          // 2048 8B-chunks per tile
            int row = idx >> 4, ch = idx & 15;
            uint32_t off = (uint32_t)(row * GST + ch * 2) * 4;
            cp8(sbase + off,             Ap + (size_t)(m0 + row) * D + kt + ch * 2);
            cp8(sbase + off + GTILE * 4, Bt + (size_t)(n0 + row) * D + kt + ch * 2);
        }
        cp_commit();
    }

    for (int c = 0; c < NCH; c++) {
        const int st = c & 1;
        if (c + 1 < NCH) cp_wait1(); else cp_wait0();
        __syncthreads();

        const uint32_t* As = smu + st * 2 * GTILE;
        const uint32_t* Bs = As + GTILE;

#pragma unroll
        for (int ks = 0; ks < KC / 8; ks++) {
            const int kk = ks * 8;
            uint32_t a[4][4], b[4][2];
            if (mode == 0) {
#pragma unroll
                for (int mf = 0; mf < 4; mf++) {
                    const int row = wm + mf * 16 + g;
                    a[mf][0] = tf32b(As[row * GST + kk + tq]);
                    a[mf][1] = tf32b(As[(row + 8) * GST + kk + tq]);
                    a[mf][2] = tf32b(As[row * GST + kk + tq + 4]);
                    a[mf][3] = tf32b(As[(row + 8) * GST + kk + tq + 4]);
                }
            } else {
#pragma unroll
                for (int mf = 0; mf < 4; mf++) {
                    const int row = wm + mf * 16 + g;
                    a[mf][0] = As[row * GST + kk + tq];
                    a[mf][1] = As[(row + 8) * GST + kk + tq];
                    a[mf][2] = As[row * GST + kk + tq + 4];
                    a[mf][3] = As[(row + 8) * GST + kk + tq + 4];
                }
            }
#pragma unroll
            for (int nf = 0; nf < 4; nf++) {
                const int col = wn + nf * 8 + g;
                b[nf][0] = Bs[col * GST + kk + tq];
                b[nf][1] = Bs[col * GST + kk + tq + 4];
            }
#pragma unroll
            for (int mf = 0; mf < 4; mf++)
#pragma unroll
                for (int nf = 0; nf < 4; nf++)
                    mma_tf32(acc[mf][nf], a[mf], b[nf]);
        }
        __syncthreads();

        // refill this stage with chunk c+2 (overlaps chunk c+1's compute)
        if (c + 2 < NCH) {
            const int kt = (c + 2) * KC;
            const uint32_t sbase = smem_u + (uint32_t)(st * 2 * GTILE) * 4;
#pragma unroll
            for (int j = 0; j < 8; j++) {
                int idx = tid + j * 256;
                int row = idx >> 4, ch = idx & 15;
                uint32_t off = (uint32_t)(row * GST + ch * 2) * 4;
                cp8(sbase + off,             Ap + (size_t)(m0 + row) * D + kt + ch * 2);
                cp8(sbase + off + GTILE * 4, Bt + (size_t)(n0 + row) * D + kt + ch * 2);
            }
            cp_commit();
        }
    }

    const float osc = (blockIdx.z == 0 && mode == 0) ? 0.125f : 1.0f;

#pragma unroll
    for (int mf = 0; mf < 4; mf++) {
#pragma unroll
        for (int nf = 0; nf < 4; nf++) {
            const int m = m0 + wm + mf * 16 + g;
            const int n = n0 + wn + nf * 8 + tq * 2;
            float bx = bias[n], by = bias[n + 1];
#pragma unroll
            for (int half = 0; half < 2; half++) {
                const int mm = m + half * 8;
                float vx = acc[mf][nf][half * 2 + 0] + bx;
                float vy = acc[mf][nf][half * 2 + 1] + by;
                if (mode == 0) {
                    vx *= osc; vy *= osc;
                    const int h = n >> 6, dk = n & 63;
                    const int bb_ = mm >> 11, s = mm & 2047;
                    if (blockIdx.z == 2) {
                        // V transposed [bh][d][s], fp16
                        __half* vtb = &g_vt[(((size_t)bb_ * H + h) * DK + dk) * S + s];
                        vtb[0] = __float2half_rn(vx);
                        vtb[S] = __float2half_rn(vy);
                    } else {
                        __half* orow = (blockIdx.z == 0 ? g_qh : g_kh)
                                       + (((size_t)bb_ * H + h) * S + s) * DK;
                        *(__half2*)&orow[dk] = __floats2half2_rn(vx, vy);
                    }
                } else {
                    const float* rr = resid + (size_t)mm * D + n;
                    float2 r2 = *(const float2*)rr;
                    float2* p = (float2*)&O1f[(size_t)mm * D + n];
                    *p = make_float2(vx + r2.x, vy + r2.y);
                }
            }
        }
    }
}

// ---------------------------------------------------------------------------
// K2: attention via fp16 mma.sync m16n8k16; cp.async fills (Q bundled with
// K0's group); K/V prefetch slid into dead phases; separate scale kernel.
// grid (16 q-tiles, 64 bh), block 256. Warp grid 4x2.
// ---------------------------------------------------------------------------
__global__ __launch_bounds__(256, 2) void attn_mma_kernel(float* __restrict__ attn_out)
{
    extern __shared__ uint32_t smu[];
    uint32_t* Qs = smu + AQ_OFF;
    uint32_t* Ks = smu + AK_OFF;
    uint32_t* Vt = smu + AV_OFF;
    uint32_t* Ps = smu + AP_OFF;
    float* rs    = (float*)(smu + ARS_OFF);
    float* sinv  = (float*)(smu + AIV_OFF);
    const uint32_t smem_u = smem_to_u32(smu);
    const uint32_t qs_u = smem_u + AQ_OFF * 4;
    const uint32_t ks_u = smem_u + AK_OFF * 4;
    const uint32_t vt_u = smem_u + AV_OFF * 4;

    const int bh = blockIdx.y;
    const int q0 = blockIdx.x * 128;
    const int tid = threadIdx.x;
    const int wid = tid >> 5, lane = tid & 31;
    const int g = lane >> 2, tq = lane & 3;
    const int wm = (wid >> 1) * 32;
    const int wn = (wid & 1) * 32;

    // prologue: Q + K(0) in one group, V(0) in a second group
#pragma unroll
    for (int i = 0; i < 4; i++) {
        int idx = tid + i * 256;
        int row = idx >> 3, ch = idx & 7;
        cp16(qs_u + (uint32_t)(row * AST + ch * 4) * 4,
             &g_qh[((size_t)bh * S + q0 + row) * DK + ch * 8]);
    }
#pragma unroll
    for (int i = 0; i < 2; i++) {
        int idx = tid + i * 256;
        int row = idx >> 3, ch = idx & 7;
        cp16(ks_u + (uint32_t)(row * AST + ch * 4) * 4,
             &g_kh[((size_t)bh * S + row) * DK + ch * 8]);
    }
    cp_commit();
#pragma unroll
    for (int i = 0; i < 2; i++) {
        int idx = tid + i * 256;
        int row = idx >> 3, ch = idx & 7;
        cp16(vt_u + (uint32_t)(row * AST + ch * 4) * 4,
             &g_vt[((size_t)bh * DK + row) * S + ch * 8]);
    }
    cp_commit();

    float cacc[2][4][4];
    float rsum[2][2] = {{0.f, 0.f}, {0.f, 0.f}};
#pragma unroll
    for (int mf = 0; mf < 2; mf++)
#pragma unroll
        for (int nf = 0; nf < 4; nf++)
#pragma unroll
            for (int r = 0; r < 4; r++) cacc[mf][nf][r] = 0.f;

    for (int kt = 0; kt < S / 64; kt++) {
        const int k0 = kt * 64;

        cp_wait1();            // Q + K(kt) arrived (V may be in flight)
        __syncthreads();

        // S = Q·K^T  (k = d = 64 -> 4 fp16 k16 steps)
        float sacc[2][4][4];
#pragma unroll
        for (int mf = 0; mf < 2; mf++)
#pragma unroll
            for (int nf = 0; nf < 4; nf++)
#pragma unroll
                for (int r = 0; r < 4; r++) sacc[mf][nf][r] = 0.f;
#pragma unroll
        for (int ks = 0; ks < 4; ks++) {
            const int kk = ks * 8;      // word offset (16 halfs)
            uint32_t a[2][4], b[4][2];
#pragma unroll
            for (int mf = 0; mf < 2; mf++) {
                const int row = wm + mf * 16 + g;
                a[mf][0] = Qs[row * AST + kk + tq];
                a[mf][1] = Qs[(row + 8) * AST + kk + tq];
                a[mf][2] = Qs[row * AST + kk + 4 + tq];
                a[mf][3] = Qs[(row + 8) * AST + kk + 4 + tq];
            }
#pragma unroll
            for (int nf = 0; nf < 4; nf++) {
                const int col = wn + nf * 8 + g;
                b[nf][0] = Ks[col * AST + kk + tq];
                b[nf][1] = Ks[col * AST + kk + 4 + tq];
            }
#pragma unroll
            for (int mf = 0; mf < 2; mf++)
#pragma unroll
                for (int nf = 0; nf < 4; nf++)
                    mma_f16(sacc[mf][nf], a[mf], b[nf]);
        }

        // exp, rowsum, E -> gmem (unnormalized), P -> smem (fp16)
#pragma unroll
        for (int mf = 0; mf < 2; mf++) {
            const int r0 = wm + mf * 16 + g;
#pragma unroll
            for (int nf = 0; nf < 4; nf++) {
                const int c0 = wn + nf * 8 + tq * 2;
                float e00 = fast_exp(sacc[mf][nf][0]);
                float e01 = fast_exp(sacc[mf][nf][1]);
                float e10 = fast_exp(sacc[mf][nf][2]);
                float e11 = fast_exp(sacc[mf][nf][3]);
                rsum[mf][0] += e00 + e01;
                rsum[mf][1] += e10 + e11;
                *(float2*)&attn_out[((size_t)bh * S + q0 + r0) * S + k0 + c0] =
                    make_float2(e00, e01);
                *(float2*)&attn_out[((size_t)bh * S + q0 + r0 + 8) * S + k0 + c0] =
                    make_float2(e10, e11);
                Ps[r0 * AST + (c0 >> 1)]       = h2u(__floats2half2_rn(e00, e01));
                Ps[(r0 + 8) * AST + (c0 >> 1)] = h2u(__floats2half2_rn(e10, e11));
            }
        }

        cp_wait0();            // V(kt) arrived
        __syncthreads();       // publish V + Ps; Ks fully consumed

        // issue K(kt+1) — overlaps the P·V phase below
        if (kt + 1 < S / 64) {
            const int nk0 = k0 + 64;
#pragma unroll
            for (int i = 0; i < 2; i++) {
                int idx = tid + i * 256;
                int row = idx >> 3, ch = idx & 7;
                cp16(ks_u + (uint32_t)(row * AST + ch * 4) * 4,
                     &g_kh[((size_t)bh * S + nk0 + row) * DK + ch * 8]);
            }
            cp_commit();
        }

        // ctx += P·V   (k = keys = 64 -> 4 fp16 k16 steps; B = Vt[d][key])
#pragma unroll
        for (int ks = 0; ks < 4; ks++) {
            const int kk = ks * 8;
            uint32_t a[2][4], b[4][2];
#pragma unroll
            for (int mf = 0; mf < 2; mf++) {
                const int row = wm + mf * 16 + g;
                a[mf][0] = Ps[row * AST + kk + tq];
                a[mf][1] = Ps[(row + 8) * AST + kk + tq];
                a[mf][2] = Ps[row * AST + kk + 4 + tq];
                a[mf][3] = Ps[(row + 8) * AST + kk + 4 + tq];
            }
#pragma unroll
            for (int nf = 0; nf < 4; nf++) {
                const int col = wn + nf * 8 + g;
                b[nf][0] = Vt[col * AST + kk + tq];
                b[nf][1] = Vt[col * AST + kk + 4 + tq];
            }
#pragma unroll
            for (int mf = 0; mf < 2; mf++)
#pragma unroll
                for (int nf = 0; nf < 4; nf++)
                    mma_f16(cacc[mf][nf], a[mf], b[nf]);
        }
        __syncthreads();       // Vt + Ps fully consumed

        // issue V(kt+1) — overlaps the next tile's QK phase
        if (kt + 1 < S / 64) {
            const int nk0 = k0 + 64;
#pragma unroll
            for (int i = 0; i < 2; i++) {
                int idx = tid + i * 256;
                int row = idx >> 3, ch = idx & 7;
                cp16(vt_u + (uint32_t)(row * AST + ch * 4) * 4,
                     &g_vt[((size_t)bh * DK + row) * S + nk0 + ch * 8]);
            }
            cp_commit();
        }
    }

    // rowsum: reduce across tq lanes (same g), publish per warp-column
#pragma unroll
    for (int mf = 0; mf < 2; mf++)
#pragma unroll
        for (int hh = 0; hh < 2; hh++) {
            float v = rsum[mf][hh];
            v += __shfl_xor_sync(0xffffffffu, v, 1);
            v += __shfl_xor_sync(0xffffffffu, v, 2);
            rsum[mf][hh] = v;
        }
    if (tq == 0) {
#pragma unroll
        for (int mf = 0; mf < 2; mf++)
#pragma unroll
            for (int hh = 0; hh < 2; hh++)
                rs[(wid & 1) * 128 + wm + mf * 16 + hh * 8 + g] = rsum[mf][hh];
    }
    __syncthreads();
    if (tid < 128) {
        float iv = 1.0f / (rs[tid] + rs[128 + tid]);
        g_rinv[(size_t)bh * S + q0 + tid] = iv;
        sinv[tid] = iv;
    }
    __syncthreads();

    // scaled ctx -> g_ctx (tf32-rounded: consumed only by fc's MMA)
    const int b_ = bh >> 4, h_ = bh & 15;
#pragma unroll
    for (int mf = 0; mf < 2; mf++) {
        const int r0 = wm + mf * 16 + g;
        const float iv0 = sinv[r0], iv1 = sinv[r0 + 8];
#pragma unroll
        for (int nf = 0; nf < 4; nf++) {
            const int c0 = wn + nf * 8 + tq * 2;
            *(float2*)&g_ctx[((size_t)b_ * S + q0 + r0) * D + h_ * DK + c0] =
                make_float2(__uint_as_float(f2tf32(cacc[mf][nf][0] * iv0)),
                            __uint_as_float(f2tf32(cacc[mf][nf][1] * iv0)));
            *(float2*)&g_ctx[((size_t)b_ * S + q0 + r0 + 8) * D + h_ * DK + c0] =
                make_float2(__uint_as_float(f2tf32(cacc[mf][nf][2] * iv1)),
                            __uint_as_float(f2tf32(cacc[mf][nf][3] * iv1)));
        }
    }
}

// ---------------------------------------------------------------------------
// K3: normalize attn in place:  attn[row][*] *= rinv[row]
// ---------------------------------------------------------------------------
__global__ __launch_bounds__(256) void attn_scale_kernel(float* __restrict__ attn)
{
    size_t idx4 = (size_t)blockIdx.x * blockDim.x + threadIdx.x;
    size_t row  = idx4 >> 9;
    float inv = g_rinv[row];
    float4* p = (float4*)attn + idx4;
    float4 v = __ldcs(p);
    v.x *= inv; v.y *= inv; v.z *= inv; v.w *= inv;
    __stcs(p, v);
}

// ---------------------------------------------------------------------------
// K5: LayerNorm over last dim (1024). One block (256 thr) per row.
// ---------------------------------------------------------------------------
__global__ __launch_bounds__(256) void ln_kernel(
    const float* __restrict__ gamma, const float* __restrict__ beta,
    float* __restrict__ out)
{
    __shared__ float s1[8], s2[8];
    __shared__ float sm_mean, sm_rstd;
    const int row = blockIdx.x;
    const int t   = threadIdx.x;
    const float* x = g_x + (size_t)row * D;

    float4 v = *(const float4*)(x + t * 4);
    float sum = v.x + v.y + v.z + v.w;
    float sq  = v.x * v.x + v.y * v.y + v.z * v.z + v.w * v.w;
#pragma unroll
    for (int m = 16; m >= 1; m >>= 1) {
        sum += __shfl_xor_sync(0xffffffffu, sum, m);
        sq  += __shfl_xor_sync(0xffffffffu, sq, m);
    }
    const int warp = t >> 5, lane = t & 31;
    if (lane == 0) { s1[warp] = sum; s2[warp] = sq; }
    __syncthreads();
    if (t == 0) {
        float a = 0.f, c = 0.f;
#pragma unroll
        for (int w = 0; w < 8; w++) { a += s1[w]; c += s2[w]; }
        float mean = a * (1.0f / D);
        float var  = c * (1.0f / D) - mean * mean;
        sm_mean = mean;
        sm_rstd = rsqrtf(var + 1e-6f);
    }
    __syncthreads();
    const float mean = sm_mean, r = sm_rstd;
    float4 g4 = *(const float4*)(gamma + t * 4);
    float4 b4 = *(const float4*)(beta + t * 4);
    float4 o;
    o.x = (v.x - mean) * r * g4.x + b4.x;
    o.y = (v.y - mean) * r * g4.y + b4.y;
    o.z = (v.z - mean) * r * g4.z + b4.z;
    o.w = (v.w - mean) * r * g4.w + b4.w;
    *(float4*)(out + (size_t)row * D + t * 4) = o;
}

// ---------------------------------------------------------------------------
extern "C" void kernel_launch(void* const* d_in, const int* in_sizes, int n_in,
                              void* d_out, int out_size)
{
    const float* q     = (const float*)d_in[0];
    const float* k     = (const float*)d_in[1];
    const float* v     = (const float*)d_in[2];
    const float* Wq    = (const float*)d_in[3];
    const float* bq    = (const float*)d_in[4];
    const float* Wfc   = (const float*)d_in[5];
    const float* bfc   = (const float*)d_in[6];
    const float* gamma = (const float*)d_in[7];
    const float* beta  = (const float*)d_in[8];

    float* out_x    = (float*)d_out;
    float* out_attn = out_x + X_ELEMS;

    cudaFuncSetAttribute(gemm_mma_kernel,
                         cudaFuncAttributeMaxDynamicSharedMemorySize, GEMM_SMEM);
    cudaFuncSetAttribute(attn_mma_kernel,
                         cudaFuncAttributeMaxDynamicSharedMemorySize, ATTN_SMEM);

    float *wqt_p, *wfct_p, *ctx_p, *x_p;
    cudaGetSymbolAddress((void**)&wqt_p,  g_wqt);
    cudaGetSymbolAddress((void**)&wfct_p, g_wfct);
    cudaGetSymbolAddress((void**)&ctx_p,  g_ctx);
    cudaGetSymbolAddress((void**)&x_p,    g_x);

    transpose_kernel<<<dim3(32, 32, 2), dim3(32, 8)>>>(Wq, Wfc);
    gemm_mma_kernel<<<dim3(8, 64, 3), 256, GEMM_SMEM>>>(
        q, k, v, wqt_p, bq, nullptr, nullptr, 0);
    attn_mma_kernel<<<dim3(16, 64), 256, ATTN_SMEM>>>(out_attn);
    attn_scale_kernel<<<(unsigned)(ATTN_ELEMS / 4 / 256), 256>>>(out_attn);
    gemm_mma_kernel<<<dim3(8, 64, 1), 256, GEMM_SMEM>>>(
        ctx_p, ctx_p, ctx_p, wfct_p, bfc, q, x_p, 1);
    ln_kernel<<<B * S, 256>>>(gamma, beta, out_x);
}

// round 12
// speedup vs baseline: 1.7191x; 1.2892x over previous
#include <cuda_runtime.h>
#include <cuda_fp16.h>
#include <cstdint>

// ---------------------------------------------------------------------------
// MultiHeadAttention (B=4, S=2048, D=1024, H=16, DK=64).
// Round 12: everything on fp16 m16n8k16 tensor cores (fp32 accumulate).
//  - convert kernel: q,k,v -> fp16 gmem; transpose emits fp16 W^T
//  - dense GEMMs: fp16 MMA, 2-stage cp.async (40KB smem), half the instrs
//  - attention: as R11 (proven), but E written fp16 to scratch; ctx -> fp16
//  - attn_scale: reads fp16 E, writes normalized fp32 to d_out (1.57GB vs 2.14)
// Output layout: d_out = [ x (8,388,608 f32) | attn (268,435,456 f32) ]
// ---------------------------------------------------------------------------

namespace {
constexpr int B  = 4;
constexpr int S  = 2048;
constexpr int D  = 1024;
constexpr int H  = 16;
constexpr int DK = 64;
constexpr size_t QH_ELEMS   = (size_t)B * H * S * DK;        // 8,388,608
constexpr size_t X_ELEMS    = (size_t)B * S * D;             // 8,388,608
constexpr size_t ATTN_ELEMS = (size_t)B * H * S * (size_t)S; // 268,435,456

// fp16 dense-GEMM tiling: CTA 128x128, warp 64x32 (2x4 warps),
// K-chunk 32 halfs (2 k16 steps), two cp.async stages.
constexpr int KC  = 32;                     // halfs per chunk
constexpr int NCH = D / KC;                 // 32 chunks
constexpr int GST = 20;                     // words/row (16 data + 4 pad); 20g+tq covers all banks
constexpr int GTILE = 128 * GST;            // words per tile (2560)
constexpr int GEMM_SMEM = 4 * GTILE * 4;    // 40,960 B

// attention smem (32-bit words), R11-proven.
constexpr int AST = 36;
constexpr int AQ_OFF = 0;                   // Qs[128][36w] fp16, pre-scaled
constexpr int AK_OFF = AQ_OFF + 128 * AST;  // Ks[64][36w]  fp16
constexpr int AV_OFF = AK_OFF + 64 * AST;   // Vt[64][36w]  fp16 (d rows, key cols)
constexpr int AP_OFF = AV_OFF + 64 * AST;   // Ps[128][36w] fp16
constexpr int ARS_OFF = AP_OFF + 128 * AST; // rs[2][128] floats
constexpr int AIV_OFF = ARS_OFF + 256;      // sinv[128] floats
constexpr int ATTN_SMEM = (AIV_OFF + 128) * 4;   // 56,832 B
}

// Scratch (allocation-free rule: __device__ globals)
__device__ __half g_qcv[X_ELEMS];          // fp16 copies of inputs
__device__ __half g_kcv[X_ELEMS];
__device__ __half g_vcv[X_ELEMS];
__device__ __half g_qh[QH_ELEMS];          // fp16, pre-scaled by 0.125
__device__ __half g_kh[QH_ELEMS];          // fp16
__device__ __half g_vt[QH_ELEMS];          // fp16; V transposed [bh][d][s]
__device__ __half g_ctx[X_ELEMS];          // fp16 (consumed by fc MMA)
__device__ __half g_eh[ATTN_ELEMS];        // fp16 unnormalized exp(S) scratch
__device__ float  g_x[X_ELEMS];            // fp32
__device__ float  g_rinv[(size_t)B * H * S];
__device__ __half g_wqt[(size_t)D * D];    // Wq^T  [N][K] fp16
__device__ __half g_wfct[(size_t)D * D];   // Wfc^T [N][K] fp16

// ---------------------------------------------------------------------------
// helpers
// ---------------------------------------------------------------------------
__device__ __forceinline__ uint32_t smem_to_u32(const void* p) {
    uint32_t a;
    asm("{ .reg .u64 t; cvta.to.shared.u64 t, %1; cvt.u32.u64 %0, t; }"
        : "=r"(a) : "l"(p));
    return a;
}
__device__ __forceinline__ uint32_t h2u(__half2 h) {
    uint32_t u;
    __builtin_memcpy(&u, &h, 4);
    return u;
}
__device__ __forceinline__ void mma_f16(float* d, const uint32_t* a, const uint32_t* b) {
    asm volatile(
        "mma.sync.aligned.m16n8k16.row.col.f32.f16.f16.f32 "
        "{%0,%1,%2,%3}, {%4,%5,%6,%7}, {%8,%9}, {%0,%1,%2,%3};"
        : "+f"(d[0]), "+f"(d[1]), "+f"(d[2]), "+f"(d[3])
        : "r"(a[0]), "r"(a[1]), "r"(a[2]), "r"(a[3]), "r"(b[0]), "r"(b[1]));
}
__device__ __forceinline__ void cp16(uint32_t dst, const void* src) {
    asm volatile("cp.async.cg.shared.global [%0], [%1], 16;" :: "r"(dst), "l"(src));
}
__device__ __forceinline__ void cp_commit() {
    asm volatile("cp.async.commit_group;" ::: "memory");
}
__device__ __forceinline__ void cp_wait0() {
    asm volatile("cp.async.wait_group 0;" ::: "memory");
}
__device__ __forceinline__ void cp_wait1() {
    asm volatile("cp.async.wait_group 1;" ::: "memory");
}
// exp via FMA pipe: magic-number range reduction + deg-5 poly (rel err ~2e-6).
__device__ __forceinline__ float fast_exp(float x) {
    const float L2E = 1.4426950408889634f;
    float t = fmaf(x, L2E, 12582912.0f);
    float n = t - 12582912.0f;
    float f = fmaf(x, L2E, -n);
    float p = 0.0013333558f;
    p = fmaf(p, f, 0.0096181291f);
    p = fmaf(p, f, 0.0555041087f);
    p = fmaf(p, f, 0.2402265069f);
    p = fmaf(p, f, 0.6931471806f);
    p = fmaf(p, f, 1.0f);
    return __int_as_float(__float_as_int(p) + (__float_as_int(t) << 23));
}

// ---------------------------------------------------------------------------
// K0a: convert q,k,v (fp32) -> fp16 gmem. blockIdx.y selects tensor.
// ---------------------------------------------------------------------------
__global__ __launch_bounds__(256) void convert_kernel(
    const float* __restrict__ q, const float* __restrict__ k,
    const float* __restrict__ v)
{
    const float* src = (blockIdx.y == 0) ? q : (blockIdx.y == 1) ? k : v;
    __half* dst = (blockIdx.y == 0) ? g_qcv : (blockIdx.y == 1) ? g_kcv : g_vcv;
    size_t i4 = (size_t)blockIdx.x * blockDim.x + threadIdx.x;   // float4 idx
    float4 fv = *((const float4*)src + i4);
    __half2 h0 = __floats2half2_rn(fv.x, fv.y);
    __half2 h1 = __floats2half2_rn(fv.z, fv.w);
    uint2 o = make_uint2(h2u(h0), h2u(h1));
    *((uint2*)dst + i4) = o;
}

// ---------------------------------------------------------------------------
// K0b: transpose Wq and Wfc once -> g_wqt / g_wfct (fp16 at store)
// ---------------------------------------------------------------------------
__global__ __launch_bounds__(256) void transpose_kernel(
    const float* __restrict__ Wq, const float* __restrict__ Wfc)
{
    __shared__ float tile[32][33];
    const float* src = blockIdx.z ? Wfc : Wq;
    __half*      dst = blockIdx.z ? g_wfct : g_wqt;
    int x = blockIdx.x * 32 + threadIdx.x;
    int y = blockIdx.y * 32 + threadIdx.y;
#pragma unroll
    for (int i = 0; i < 32; i += 8)
        tile[threadIdx.y + i][threadIdx.x] = src[(size_t)(y + i) * D + x];
    __syncthreads();
    int tx = blockIdx.y * 32 + threadIdx.x;
    int ty = blockIdx.x * 32 + threadIdx.y;
#pragma unroll
    for (int i = 0; i < 32; i += 8)
        dst[(size_t)(ty + i) * D + tx] =
            __float2half_rn(tile[threadIdx.x][threadIdx.y + i]);
}

// ---------------------------------------------------------------------------
// K1/K4: fp16 mma.sync GEMM, 2-stage cp.async pipeline.
// Y[m,n] = A[m,:] . Bt[n,:]  (+bias[, +resid])
// mode 0: proj -> fp16 outputs (z=0 qh scaled by 0.125, z=1 kh, z=2 Vt).
// mode 1: fc (A = g_ctx fp16, B = Wfc^T fp16) -> fp32 g_x + resid.
// ---------------------------------------------------------------------------
__global__ __launch_bounds__(256) void gemm_f16_kernel(
    const __half* __restrict__ A0, const __half* __restrict__ A1,
    const __half* __restrict__ A2, const __half* __restrict__ Bt,
    const float* __restrict__ bias, const float* __restrict__ resid,
    float* __restrict__ O1f, int mode)
{
    extern __shared__ uint32_t smu[];
    const uint32_t smem_u = smem_to_u32(smu);

    const int tid  = threadIdx.x;
    const int wid  = tid >> 5, lane = tid & 31;
    const int g    = lane >> 2, tq = lane & 3;
    const int wm   = (wid >> 2) * 64;
    const int wn   = (wid & 3) * 32;
    const int n0   = blockIdx.x * 128;
    const int m0   = blockIdx.y * 128;

    const __half* Ap;
    if (blockIdx.z == 0)      Ap = A0;
    else if (blockIdx.z == 1) Ap = A1;
    else                      Ap = A2;

    float acc[4][4][4];
#pragma unroll
    for (int i = 0; i < 4; i++)
#pragma unroll
        for (int j = 0; j < 4; j++)
#pragma unroll
            for (int r = 0; r < 4; r++) acc[i][j][r] = 0.f;

    // prologue: issue chunks 0 (stage 0) and 1 (stage 1)
    // each tile: 128 rows x 32 halfs = 512 16B-chunks, 2 per thread
#pragma unroll
    for (int c0 = 0; c0 < 2; c0++) {
        const int kt = c0 * KC;
        const uint32_t sbase = smem_u + (uint32_t)(c0 * 2 * GTILE) * 4;
#pragma unroll
        for (int j = 0; j < 2; j++) {
            int idx = tid + j * 256;
            int row = idx >> 2, ch = idx & 3;
            uint32_t off = (uint32_t)(row * GST + ch * 4) * 4;
            cp16(sbase + off,             Ap + (size_t)(m0 + row) * D + kt + ch * 8);
            cp16(sbase + off + GTILE * 4, Bt + (size_t)(n0 + row) * D + kt + ch * 8);
        }
        cp_commit();
    }

    for (int c = 0; c < NCH; c++) {
        const int st = c & 1;
        if (c + 1 < NCH) cp_wait1(); else cp_wait0();
        __syncthreads();

        const uint32_t* As = smu + st * 2 * GTILE;
        const uint32_t* Bs = As + GTILE;

#pragma unroll
        for (int ks = 0; ks < 2; ks++) {       // 2 k16 steps per 32-half chunk
            const int kk = ks * 8;             // word offset
            uint32_t a[4][4], b[4][2];
#pragma unroll
            for (int mf = 0; mf < 4; mf++) {
                const int row = wm + mf * 16 + g;
                a[mf][0] = As[row * GST + kk + tq];
                a[mf][1] = As[(row + 8) * GST + kk + tq];
                a[mf][2] = As[row * GST + kk + 4 + tq];
                a[mf][3] = As[(row + 8) * GST + kk + 4 + tq];
            }
#pragma unroll
            for (int nf = 0; nf < 4; nf++) {
                const int col = wn + nf * 8 + g;
                b[nf][0] = Bs[col * GST + kk + tq];
                b[nf][1] = Bs[col * GST + kk + 4 + tq];
            }
#pragma unroll
            for (int mf = 0; mf < 4; mf++)
#pragma unroll
                for (int nf = 0; nf < 4; nf++)
                    mma_f16(acc[mf][nf], a[mf], b[nf]);
        }
        __syncthreads();

        // refill this stage with chunk c+2 (overlaps chunk c+1's compute)
        if (c + 2 < NCH) {
            const int kt = (c + 2) * KC;
            const uint32_t sbase = smem_u + (uint32_t)(st * 2 * GTILE) * 4;
#pragma unroll
            for (int j = 0; j < 2; j++) {
                int idx = tid + j * 256;
                int row = idx >> 2, ch = idx & 3;
                uint32_t off = (uint32_t)(row * GST + ch * 4) * 4;
                cp16(sbase + off,             Ap + (size_t)(m0 + row) * D + kt + ch * 8);
                cp16(sbase + off + GTILE * 4, Bt + (size_t)(n0 + row) * D + kt + ch * 8);
            }
            cp_commit();
        }
    }

    const float osc = (blockIdx.z == 0 && mode == 0) ? 0.125f : 1.0f;

#pragma unroll
    for (int mf = 0; mf < 4; mf++) {
#pragma unroll
        for (int nf = 0; nf < 4; nf++) {
            const int m = m0 + wm + mf * 16 + g;
            const int n = n0 + wn + nf * 8 + tq * 2;
            float bx = bias[n], by = bias[n + 1];
#pragma unroll
            for (int half = 0; half < 2; half++) {
                const int mm = m + half * 8;
                float vx = acc[mf][nf][half * 2 + 0] + bx;
                float vy = acc[mf][nf][half * 2 + 1] + by;
                if (mode == 0) {
                    vx *= osc; vy *= osc;
                    const int h = n >> 6, dk = n & 63;
                    const int bb_ = mm >> 11, s = mm & 2047;
                    if (blockIdx.z == 2) {
                        __half* vtb = &g_vt[(((size_t)bb_ * H + h) * DK + dk) * S + s];
                        vtb[0] = __float2half_rn(vx);
                        vtb[S] = __float2half_rn(vy);
                    } else {
                        __half* orow = (blockIdx.z == 0 ? g_qh : g_kh)
                                       + (((size_t)bb_ * H + h) * S + s) * DK;
                        *(__half2*)&orow[dk] = __floats2half2_rn(vx, vy);
                    }
                } else {
                    const float* rr = resid + (size_t)mm * D + n;
                    float2 r2 = *(const float2*)rr;
                    float2* p = (float2*)&O1f[(size_t)mm * D + n];
                    *p = make_float2(vx + r2.x, vy + r2.y);
                }
            }
        }
    }
}

// ---------------------------------------------------------------------------
// K2: attention via fp16 mma.sync m16n8k16 (R11-proven). E written fp16 to
// g_eh scratch; ctx written fp16 to g_ctx. grid (16 q-tiles, 64 bh).
// ---------------------------------------------------------------------------
__global__ __launch_bounds__(256, 2) void attn_mma_kernel()
{
    extern __shared__ uint32_t smu[];
    uint32_t* Qs = smu + AQ_OFF;
    uint32_t* Ks = smu + AK_OFF;
    uint32_t* Vt = smu + AV_OFF;
    uint32_t* Ps = smu + AP_OFF;
    float* rs    = (float*)(smu + ARS_OFF);
    float* sinv  = (float*)(smu + AIV_OFF);
    const uint32_t smem_u = smem_to_u32(smu);
    const uint32_t qs_u = smem_u + AQ_OFF * 4;
    const uint32_t ks_u = smem_u + AK_OFF * 4;
    const uint32_t vt_u = smem_u + AV_OFF * 4;

    const int bh = blockIdx.y;
    const int q0 = blockIdx.x * 128;
    const int tid = threadIdx.x;
    const int wid = tid >> 5, lane = tid & 31;
    const int g = lane >> 2, tq = lane & 3;
    const int wm = (wid >> 1) * 32;
    const int wn = (wid & 1) * 32;

    // prologue: Q + K(0) in one group, V(0) in a second group
#pragma unroll
    for (int i = 0; i < 4; i++) {
        int idx = tid + i * 256;
        int row = idx >> 3, ch = idx & 7;
        cp16(qs_u + (uint32_t)(row * AST + ch * 4) * 4,
             &g_qh[((size_t)bh * S + q0 + row) * DK + ch * 8]);
    }
#pragma unroll
    for (int i = 0; i < 2; i++) {
        int idx = tid + i * 256;
        int row = idx >> 3, ch = idx & 7;
        cp16(ks_u + (uint32_t)(row * AST + ch * 4) * 4,
             &g_kh[((size_t)bh * S + row) * DK + ch * 8]);
    }
    cp_commit();
#pragma unroll
    for (int i = 0; i < 2; i++) {
        int idx = tid + i * 256;
        int row = idx >> 3, ch = idx & 7;
        cp16(vt_u + (uint32_t)(row * AST + ch * 4) * 4,
             &g_vt[((size_t)bh * DK + row) * S + ch * 8]);
    }
    cp_commit();

    float cacc[2][4][4];
    float rsum[2][2] = {{0.f, 0.f}, {0.f, 0.f}};
#pragma unroll
    for (int mf = 0; mf < 2; mf++)
#pragma unroll
        for (int nf = 0; nf < 4; nf++)
#pragma unroll
            for (int r = 0; r < 4; r++) cacc[mf][nf][r] = 0.f;

    for (int kt = 0; kt < S / 64; kt++) {
        const int k0 = kt * 64;

        cp_wait1();            // Q + K(kt) arrived (V may be in flight)
        __syncthreads();

        // S = Q·K^T  (k = d = 64 -> 4 fp16 k16 steps)
        float sacc[2][4][4];
#pragma unroll
        for (int mf = 0; mf < 2; mf++)
#pragma unroll
            for (int nf = 0; nf < 4; nf++)
#pragma unroll
                for (int r = 0; r < 4; r++) sacc[mf][nf][r] = 0.f;
#pragma unroll
        for (int ks = 0; ks < 4; ks++) {
            const int kk = ks * 8;      // word offset (16 halfs)
            uint32_t a[2][4], b[4][2];
#pragma unroll
            for (int mf = 0; mf < 2; mf++) {
                const int row = wm + mf * 16 + g;
                a[mf][0] = Qs[row * AST + kk + tq];
                a[mf][1] = Qs[(row + 8) * AST + kk + tq];
                a[mf][2] = Qs[row * AST + kk + 4 + tq];
                a[mf][3] = Qs[(row + 8) * AST + kk + 4 + tq];
            }
#pragma unroll
            for (int nf = 0; nf < 4; nf++) {
                const int col = wn + nf * 8 + g;
                b[nf][0] = Ks[col * AST + kk + tq];
                b[nf][1] = Ks[col * AST + kk + 4 + tq];
            }
#pragma unroll
            for (int mf = 0; mf < 2; mf++)
#pragma unroll
                for (int nf = 0; nf < 4; nf++)
                    mma_f16(sacc[mf][nf], a[mf], b[nf]);
        }

        // exp, rowsum, E -> g_eh (fp16 unnormalized), P -> smem (fp16)
#pragma unroll
        for (int mf = 0; mf < 2; mf++) {
            const int r0 = wm + mf * 16 + g;
#pragma unroll
            for (int nf = 0; nf < 4; nf++) {
                const int c0 = wn + nf * 8 + tq * 2;
                float e00 = fast_exp(sacc[mf][nf][0]);
                float e01 = fast_exp(sacc[mf][nf][1]);
                float e10 = fast_exp(sacc[mf][nf][2]);
                float e11 = fast_exp(sacc[mf][nf][3]);
                rsum[mf][0] += e00 + e01;
                rsum[mf][1] += e10 + e11;
                uint32_t p01 = h2u(__floats2half2_rn(e00, e01));
                uint32_t p23 = h2u(__floats2half2_rn(e10, e11));
                *(uint32_t*)&g_eh[((size_t)bh * S + q0 + r0) * S + k0 + c0] = p01;
                *(uint32_t*)&g_eh[((size_t)bh * S + q0 + r0 + 8) * S + k0 + c0] = p23;
                Ps[r0 * AST + (c0 >> 1)]       = p01;
                Ps[(r0 + 8) * AST + (c0 >> 1)] = p23;
            }
        }

        cp_wait0();            // V(kt) arrived
        __syncthreads();       // publish V + Ps; Ks fully consumed

        // issue K(kt+1) — overlaps the P·V phase below
        if (kt + 1 < S / 64) {
            const int nk0 = k0 + 64;
#pragma unroll
            for (int i = 0; i < 2; i++) {
                int idx = tid + i * 256;
                int row = idx >> 3, ch = idx & 7;
                cp16(ks_u + (uint32_t)(row * AST + ch * 4) * 4,
                     &g_kh[((size_t)bh * S + nk0 + row) * DK + ch * 8]);
            }
            cp_commit();
        }

        // ctx += P·V   (k = keys = 64 -> 4 fp16 k16 steps; B = Vt[d][key])
#pragma unroll
        for (int ks = 0; ks < 4; ks++) {
            const int kk = ks * 8;
            uint32_t a[2][4], b[4][2];
#pragma unroll
            for (int mf = 0; mf < 2; mf++) {
                const int row = wm + mf * 16 + g;
                a[mf][0] = Ps[row * AST + kk + tq];
                a[mf][1] = Ps[(row + 8) * AST + kk + tq];
                a[mf][2] = Ps[row * AST + kk + 4 + tq];
                a[mf][3] = Ps[(row + 8) * AST + kk + 4 + tq];
            }
#pragma unroll
            for (int nf = 0; nf < 4; nf++) {
                const int col = wn + nf * 8 + g;
                b[nf][0] = Vt[col * AST + kk + tq];
                b[nf][1] = Vt[col * AST + kk + 4 + tq];
            }
#pragma unroll
            for (int mf = 0; mf < 2; mf++)
#pragma unroll
                for (int nf = 0; nf < 4; nf++)
                    mma_f16(cacc[mf][nf], a[mf], b[nf]);
        }
        __syncthreads();       // Vt + Ps fully consumed

        // issue V(kt+1) — overlaps the next tile's QK phase
        if (kt + 1 < S / 64) {
            const int nk0 = k0 + 64;
#pragma unroll
            for (int i = 0; i < 2; i++) {
                int idx = tid + i * 256;
                int row = idx >> 3, ch = idx & 7;
                cp16(vt_u + (uint32_t)(row * AST + ch * 4) * 4,
                     &g_vt[((size_t)bh * DK + row) * S + nk0 + ch * 8]);
            }
            cp_commit();
        }
    }

    // rowsum: reduce across tq lanes (same g), publish per warp-column
#pragma unroll
    for (int mf = 0; mf < 2; mf++)
#pragma unroll
        for (int hh = 0; hh < 2; hh++) {
            float v = rsum[mf][hh];
            v += __shfl_xor_sync(0xffffffffu, v, 1);
            v += __shfl_xor_sync(0xffffffffu, v, 2);
            rsum[mf][hh] = v;
        }
    if (tq == 0) {
#pragma unroll
        for (int mf = 0; mf < 2; mf++)
#pragma unroll
            for (int hh = 0; hh < 2; hh++)
                rs[(wid & 1) * 128 + wm + mf * 16 + hh * 8 + g] = rsum[mf][hh];
    }
    __syncthreads();
    if (tid < 128) {
        float iv = 1.0f / (rs[tid] + rs[128 + tid]);
        g_rinv[(size_t)bh * S + q0 + tid] = iv;
        sinv[tid] = iv;
    }
    __syncthreads();

    // scaled ctx -> g_ctx (fp16: consumed only by fc's fp16 MMA)
    const int b_ = bh >> 4, h_ = bh & 15;
#pragma unroll
    for (int mf = 0; mf < 2; mf++) {
        const int r0 = wm + mf * 16 + g;
        const float iv0 = sinv[r0], iv1 = sinv[r0 + 8];
#pragma unroll
        for (int nf = 0; nf < 4; nf++) {
            const int c0 = wn + nf * 8 + tq * 2;
            *(__half2*)&g_ctx[((size_t)b_ * S + q0 + r0) * D + h_ * DK + c0] =
                __floats2half2_rn(cacc[mf][nf][0] * iv0, cacc[mf][nf][1] * iv0);
            *(__half2*)&g_ctx[((size_t)b_ * S + q0 + r0 + 8) * D + h_ * DK + c0] =
                __floats2half2_rn(cacc[mf][nf][2] * iv1, cacc[mf][nf][3] * iv1);
        }
    }
}

// ---------------------------------------------------------------------------
// K3: normalize: attn_out[row][*] = half2float(g_eh[row][*]) * rinv[row]
// reads 0.5GB fp16, writes 1.07GB fp32 (was 2.14GB RMW fp32).
// ---------------------------------------------------------------------------
__global__ __launch_bounds__(256) void attn_scale_kernel(float* __restrict__ attn)
{
    size_t idx4 = (size_t)blockIdx.x * blockDim.x + threadIdx.x;  // 4-elem idx
    size_t row  = idx4 >> 9;                                      // 512 groups/row
    float inv = g_rinv[row];
    uint2 e = __ldcs((const uint2*)g_eh + idx4);
    __half2 h0, h1;
    __builtin_memcpy(&h0, &e.x, 4);
    __builtin_memcpy(&h1, &e.y, 4);
    float2 f0 = __half22float2(h0);
    float2 f1 = __half22float2(h1);
    float4 v = make_float4(f0.x * inv, f0.y * inv, f1.x * inv, f1.y * inv);
    __stcs((float4*)attn + idx4, v);
}

// ---------------------------------------------------------------------------
// K5: LayerNorm over last dim (1024). One block (256 thr) per row.
// ---------------------------------------------------------------------------
__global__ __launch_bounds__(256) void ln_kernel(
    const float* __restrict__ gamma, const float* __restrict__ beta,
    float* __restrict__ out)
{
    __shared__ float s1[8], s2[8];
    __shared__ float sm_mean, sm_rstd;
    const int row = blockIdx.x;
    const int t   = threadIdx.x;
    const float* x = g_x + (size_t)row * D;

    float4 v = *(const float4*)(x + t * 4);
    float sum = v.x + v.y + v.z + v.w;
    float sq  = v.x * v.x + v.y * v.y + v.z * v.z + v.w * v.w;
#pragma unroll
    for (int m = 16; m >= 1; m >>= 1) {
        sum += __shfl_xor_sync(0xffffffffu, sum, m);
        sq  += __shfl_xor_sync(0xffffffffu, sq, m);
    }
    const int warp = t >> 5, lane = t & 31;
    if (lane == 0) { s1[warp] = sum; s2[warp] = sq; }
    __syncthreads();
    if (t == 0) {
        float a = 0.f, c = 0.f;
#pragma unroll
        for (int w = 0; w < 8; w++) { a += s1[w]; c += s2[w]; }
        float mean = a * (1.0f / D);
        float var  = c * (1.0f / D) - mean * mean;
        sm_mean = mean;
        sm_rstd = rsqrtf(var + 1e-6f);
    }
    __syncthreads();
    const float mean = sm_mean, r = sm_rstd;
    float4 g4 = *(const float4*)(gamma + t * 4);
    float4 b4 = *(const float4*)(beta + t * 4);
    float4 o;
    o.x = (v.x - mean) * r * g4.x + b4.x;
    o.y = (v.y - mean) * r * g4.y + b4.y;
    o.z = (v.z - mean) * r * g4.z + b4.z;
    o.w = (v.w - mean) * r * g4.w + b4.w;
    *(float4*)(out + (size_t)row * D + t * 4) = o;
}

// ---------------------------------------------------------------------------
extern "C" void kernel_launch(void* const* d_in, const int* in_sizes, int n_in,
                              void* d_out, int out_size)
{
    const float* q     = (const float*)d_in[0];
    const float* k     = (const float*)d_in[1];
    const float* v     = (const float*)d_in[2];
    const float* Wq    = (const float*)d_in[3];
    const float* bq    = (const float*)d_in[4];
    const float* Wfc   = (const float*)d_in[5];
    const float* bfc   = (const float*)d_in[6];
    const float* gamma = (const float*)d_in[7];
    const float* beta  = (const float*)d_in[8];

    float* out_x    = (float*)d_out;
    float* out_attn = out_x + X_ELEMS;

    cudaFuncSetAttribute(gemm_f16_kernel,
                         cudaFuncAttributeMaxDynamicSharedMemorySize, GEMM_SMEM);
    cudaFuncSetAttribute(attn_mma_kernel,
                         cudaFuncAttributeMaxDynamicSharedMemorySize, ATTN_SMEM);

    __half *qcv_p, *kcv_p, *vcv_p, *wqt_p, *wfct_p, *ctx_p;
    float *x_p;
    cudaGetSymbolAddress((void**)&qcv_p,  g_qcv);
    cudaGetSymbolAddress((void**)&kcv_p,  g_kcv);
    cudaGetSymbolAddress((void**)&vcv_p,  g_vcv);
    cudaGetSymbolAddress((void**)&wqt_p,  g_wqt);
    cudaGetSymbolAddress((void**)&wfct_p, g_wfct);
    cudaGetSymbolAddress((void**)&ctx_p,  g_ctx);
    cudaGetSymbolAddress((void**)&x_p,    g_x);

    convert_kernel<<<dim3((unsigned)(X_ELEMS / 4 / 256), 3), 256>>>(q, k, v);
    transpose_kernel<<<dim3(32, 32, 2), dim3(32, 8)>>>(Wq, Wfc);
    gemm_f16_kernel<<<dim3(8, 64, 3), 256, GEMM_SMEM>>>(
        qcv_p, kcv_p, vcv_p, wqt_p, bq, nullptr, nullptr, 0);
    attn_mma_kernel<<<dim3(16, 64), 256, ATTN_SMEM>>>();
    attn_scale_kernel<<<(unsigned)(ATTN_ELEMS / 4 / 256), 256>>>(out_attn);
    gemm_f16_kernel<<<dim3(8, 64, 1), 256, GEMM_SMEM>>>(
        ctx_p, ctx_p, ctx_p, wfct_p, bfc, q, x_p, 1);
    ln_kernel<<<B * S, 256>>>(gamma, beta, out_x);
}

// round 13
// speedup vs baseline: 1.7930x; 1.0430x over previous
#include <cuda_runtime.h>
#include <cuda_fp16.h>
#include <cstdint>

// ---------------------------------------------------------------------------
// MultiHeadAttention (B=4, S=2048, D=1024, H=16, DK=64).
// Round 13: R12 (full fp16 m16n8k16 pipeline) + ldmatrix fragment loads
// everywhere (4x fewer A-frag LDS, 2x fewer B-frag LDS; bit-identical data).
// Output layout: d_out = [ x (8,388,608 f32) | attn (268,435,456 f32) ]
// ---------------------------------------------------------------------------

namespace {
constexpr int B  = 4;
constexpr int S  = 2048;
constexpr int D  = 1024;
constexpr int H  = 16;
constexpr int DK = 64;
constexpr size_t QH_ELEMS   = (size_t)B * H * S * DK;        // 8,388,608
constexpr size_t X_ELEMS    = (size_t)B * S * D;             // 8,388,608
constexpr size_t ATTN_ELEMS = (size_t)B * H * S * (size_t)S; // 268,435,456

// fp16 dense-GEMM tiling: CTA 128x128, warp 64x32 (2x4 warps),
// K-chunk 32 halfs (2 k16 steps), two cp.async stages.
constexpr int KC  = 32;                     // halfs per chunk
constexpr int NCH = D / KC;                 // 32 chunks
constexpr int GST = 20;                     // words/row; 8-row ldmatrix conflict-free
constexpr int GTILE = 128 * GST;            // words per tile (2560)
constexpr int GEMM_SMEM = 4 * GTILE * 4;    // 40,960 B

// attention smem (32-bit words), R11/R12-proven.
constexpr int AST = 36;
constexpr int AQ_OFF = 0;                   // Qs[128][36w] fp16, pre-scaled
constexpr int AK_OFF = AQ_OFF + 128 * AST;  // Ks[64][36w]  fp16
constexpr int AV_OFF = AK_OFF + 64 * AST;   // Vt[64][36w]  fp16 (d rows, key cols)
constexpr int AP_OFF = AV_OFF + 64 * AST;   // Ps[128][36w] fp16
constexpr int ARS_OFF = AP_OFF + 128 * AST; // rs[2][128] floats
constexpr int AIV_OFF = ARS_OFF + 256;      // sinv[128] floats
constexpr int ATTN_SMEM = (AIV_OFF + 128) * 4;   // 56,832 B
}

// Scratch (allocation-free rule: __device__ globals)
__device__ __half g_qcv[X_ELEMS];          // fp16 copies of inputs
__device__ __half g_kcv[X_ELEMS];
__device__ __half g_vcv[X_ELEMS];
__device__ __half g_qh[QH_ELEMS];          // fp16, pre-scaled by 0.125
__device__ __half g_kh[QH_ELEMS];          // fp16
__device__ __half g_vt[QH_ELEMS];          // fp16; V transposed [bh][d][s]
__device__ __half g_ctx[X_ELEMS];          // fp16 (consumed by fc MMA)
__device__ __half g_eh[ATTN_ELEMS];        // fp16 unnormalized exp(S) scratch
__device__ float  g_x[X_ELEMS];            // fp32
__device__ float  g_rinv[(size_t)B * H * S];
__device__ __half g_wqt[(size_t)D * D];    // Wq^T  [N][K] fp16
__device__ __half g_wfct[(size_t)D * D];   // Wfc^T [N][K] fp16

// ---------------------------------------------------------------------------
// helpers
// ---------------------------------------------------------------------------
__device__ __forceinline__ uint32_t smem_to_u32(const void* p) {
    uint32_t a;
    asm("{ .reg .u64 t; cvta.to.shared.u64 t, %1; cvt.u32.u64 %0, t; }"
        : "=r"(a) : "l"(p));
    return a;
}
__device__ __forceinline__ uint32_t h2u(__half2 h) {
    uint32_t u;
    __builtin_memcpy(&u, &h, 4);
    return u;
}
__device__ __forceinline__ void mma_f16(float* d, const uint32_t* a, const uint32_t* b) {
    asm volatile(
        "mma.sync.aligned.m16n8k16.row.col.f32.f16.f16.f32 "
        "{%0,%1,%2,%3}, {%4,%5,%6,%7}, {%8,%9}, {%0,%1,%2,%3};"
        : "+f"(d[0]), "+f"(d[1]), "+f"(d[2]), "+f"(d[3])
        : "r"(a[0]), "r"(a[1]), "r"(a[2]), "r"(a[3]), "r"(b[0]), "r"(b[1]));
}
__device__ __forceinline__ void ldsm_x4(uint32_t* r, uint32_t addr) {
    asm volatile("ldmatrix.sync.aligned.m8n8.x4.shared.b16 {%0,%1,%2,%3}, [%4];"
        : "=r"(r[0]), "=r"(r[1]), "=r"(r[2]), "=r"(r[3]) : "r"(addr));
}
__device__ __forceinline__ void ldsm_x2(uint32_t* r, uint32_t addr) {
    asm volatile("ldmatrix.sync.aligned.m8n8.x2.shared.b16 {%0,%1}, [%2];"
        : "=r"(r[0]), "=r"(r[1]) : "r"(addr));
}
__device__ __forceinline__ void cp16(uint32_t dst, const void* src) {
    asm volatile("cp.async.cg.shared.global [%0], [%1], 16;" :: "r"(dst), "l"(src));
}
__device__ __forceinline__ void cp_commit() {
    asm volatile("cp.async.commit_group;" ::: "memory");
}
__device__ __forceinline__ void cp_wait0() {
    asm volatile("cp.async.wait_group 0;" ::: "memory");
}
__device__ __forceinline__ void cp_wait1() {
    asm volatile("cp.async.wait_group 1;" ::: "memory");
}
// exp via FMA pipe: magic-number range reduction + deg-5 poly (rel err ~2e-6).
__device__ __forceinline__ float fast_exp(float x) {
    const float L2E = 1.4426950408889634f;
    float t = fmaf(x, L2E, 12582912.0f);
    float n = t - 12582912.0f;
    float f = fmaf(x, L2E, -n);
    float p = 0.0013333558f;
    p = fmaf(p, f, 0.0096181291f);
    p = fmaf(p, f, 0.0555041087f);
    p = fmaf(p, f, 0.2402265069f);
    p = fmaf(p, f, 0.6931471806f);
    p = fmaf(p, f, 1.0f);
    return __int_as_float(__float_as_int(p) + (__float_as_int(t) << 23));
}

// ---------------------------------------------------------------------------
// K0a: convert q,k,v (fp32) -> fp16 gmem. blockIdx.y selects tensor.
// ---------------------------------------------------------------------------
__global__ __launch_bounds__(256) void convert_kernel(
    const float* __restrict__ q, const float* __restrict__ k,
    const float* __restrict__ v)
{
    const float* src = (blockIdx.y == 0) ? q : (blockIdx.y == 1) ? k : v;
    __half* dst = (blockIdx.y == 0) ? g_qcv : (blockIdx.y == 1) ? g_kcv : g_vcv;
    size_t i4 = (size_t)blockIdx.x * blockDim.x + threadIdx.x;   // float4 idx
    float4 fv = *((const float4*)src + i4);
    __half2 h0 = __floats2half2_rn(fv.x, fv.y);
    __half2 h1 = __floats2half2_rn(fv.z, fv.w);
    uint2 o = make_uint2(h2u(h0), h2u(h1));
    *((uint2*)dst + i4) = o;
}

// ---------------------------------------------------------------------------
// K0b: transpose Wq and Wfc once -> g_wqt / g_wfct (fp16 at store)
// ---------------------------------------------------------------------------
__global__ __launch_bounds__(256) void transpose_kernel(
    const float* __restrict__ Wq, const float* __restrict__ Wfc)
{
    __shared__ float tile[32][33];
    const float* src = blockIdx.z ? Wfc : Wq;
    __half*      dst = blockIdx.z ? g_wfct : g_wqt;
    int x = blockIdx.x * 32 + threadIdx.x;
    int y = blockIdx.y * 32 + threadIdx.y;
#pragma unroll
    for (int i = 0; i < 32; i += 8)
        tile[threadIdx.y + i][threadIdx.x] = src[(size_t)(y + i) * D + x];
    __syncthreads();
    int tx = blockIdx.y * 32 + threadIdx.x;
    int ty = blockIdx.x * 32 + threadIdx.y;
#pragma unroll
    for (int i = 0; i < 32; i += 8)
        dst[(size_t)(ty + i) * D + tx] =
            __float2half_rn(tile[threadIdx.x][threadIdx.y + i]);
}

// ---------------------------------------------------------------------------
// K1/K4: fp16 mma.sync GEMM, 2-stage cp.async pipeline, ldmatrix frags.
// Y[m,n] = A[m,:] . Bt[n,:]  (+bias[, +resid])
// mode 0: proj -> fp16 outputs (z=0 qh scaled by 0.125, z=1 kh, z=2 Vt).
// mode 1: fc (A = g_ctx fp16, B = Wfc^T fp16) -> fp32 g_x + resid.
// ---------------------------------------------------------------------------
__global__ __launch_bounds__(256) void gemm_f16_kernel(
    const __half* __restrict__ A0, const __half* __restrict__ A1,
    const __half* __restrict__ A2, const __half* __restrict__ Bt,
    const float* __restrict__ bias, const float* __restrict__ resid,
    float* __restrict__ O1f, int mode)
{
    extern __shared__ uint32_t smu[];
    const uint32_t smem_u = smem_to_u32(smu);

    const int tid  = threadIdx.x;
    const int wid  = tid >> 5, lane = tid & 31;
    const int g    = lane >> 2, tq = lane & 3;
    const int wm   = (wid >> 2) * 64;
    const int wn   = (wid & 3) * 32;
    const int n0   = blockIdx.x * 128;
    const int m0   = blockIdx.y * 128;

    // ldmatrix per-lane address components
    const int mat  = lane >> 3;           // 0..3 (A x4 groups)
    const int lrow = lane & 7;
    const int matb = (lane >> 3) & 1;     // B x2 groups
    const uint32_t aoff =
        ((uint32_t)((wm + (mat & 1) * 8 + lrow) * GST + (mat >> 1) * 4)) * 4;
    const uint32_t boff =
        ((uint32_t)((wn + lrow) * GST + matb * 4)) * 4;

    const __half* Ap;
    if (blockIdx.z == 0)      Ap = A0;
    else if (blockIdx.z == 1) Ap = A1;
    else                      Ap = A2;

    float acc[4][4][4];
#pragma unroll
    for (int i = 0; i < 4; i++)
#pragma unroll
        for (int j = 0; j < 4; j++)
#pragma unroll
            for (int r = 0; r < 4; r++) acc[i][j][r] = 0.f;

    // prologue: issue chunks 0 (stage 0) and 1 (stage 1)
#pragma unroll
    for (int c0 = 0; c0 < 2; c0++) {
        const int kt = c0 * KC;
        const uint32_t sbase = smem_u + (uint32_t)(c0 * 2 * GTILE) * 4;
#pragma unroll
        for (int j = 0; j < 2; j++) {
            int idx = tid + j * 256;
            int row = idx >> 2, ch = idx & 3;
            uint32_t off = (uint32_t)(row * GST + ch * 4) * 4;
            cp16(sbase + off,             Ap + (size_t)(m0 + row) * D + kt + ch * 8);
            cp16(sbase + off + GTILE * 4, Bt + (size_t)(n0 + row) * D + kt + ch * 8);
        }
        cp_commit();
    }

    for (int c = 0; c < NCH; c++) {
        const int st = c & 1;
        if (c + 1 < NCH) cp_wait1(); else cp_wait0();
        __syncthreads();

        const uint32_t abase = smem_u + (uint32_t)(st * 2 * GTILE) * 4 + aoff;
        const uint32_t bbase = smem_u + (uint32_t)(st * 2 * GTILE + GTILE) * 4 + boff;

#pragma unroll
        for (int ks = 0; ks < 2; ks++) {       // 2 k16 steps per 32-half chunk
            const int kk = ks * 8;             // word offset
            uint32_t a[4][4], b[4][2];
#pragma unroll
            for (int mf = 0; mf < 4; mf++)
                ldsm_x4(a[mf], abase + (uint32_t)(mf * 16 * GST + kk) * 4);
#pragma unroll
            for (int nf = 0; nf < 4; nf++)
                ldsm_x2(b[nf], bbase + (uint32_t)(nf * 8 * GST + kk) * 4);
#pragma unroll
            for (int mf = 0; mf < 4; mf++)
#pragma unroll
                for (int nf = 0; nf < 4; nf++)
                    mma_f16(acc[mf][nf], a[mf], b[nf]);
        }
        __syncthreads();

        // refill this stage with chunk c+2 (overlaps chunk c+1's compute)
        if (c + 2 < NCH) {
            const int kt = (c + 2) * KC;
            const uint32_t sbase = smem_u + (uint32_t)(st * 2 * GTILE) * 4;
#pragma unroll
            for (int j = 0; j < 2; j++) {
                int idx = tid + j * 256;
                int row = idx >> 2, ch = idx & 3;
                uint32_t off = (uint32_t)(row * GST + ch * 4) * 4;
                cp16(sbase + off,             Ap + (size_t)(m0 + row) * D + kt + ch * 8);
                cp16(sbase + off + GTILE * 4, Bt + (size_t)(n0 + row) * D + kt + ch * 8);
            }
            cp_commit();
        }
    }

    const float osc = (blockIdx.z == 0 && mode == 0) ? 0.125f : 1.0f;

#pragma unroll
    for (int mf = 0; mf < 4; mf++) {
#pragma unroll
        for (int nf = 0; nf < 4; nf++) {
            const int m = m0 + wm + mf * 16 + g;
            const int n = n0 + wn + nf * 8 + tq * 2;
            float bx = bias[n], by = bias[n + 1];
#pragma unroll
            for (int half = 0; half < 2; half++) {
                const int mm = m + half * 8;
                float vx = acc[mf][nf][half * 2 + 0] + bx;
                float vy = acc[mf][nf][half * 2 + 1] + by;
                if (mode == 0) {
                    vx *= osc; vy *= osc;
                    const int h = n >> 6, dk = n & 63;
                    const int bb_ = mm >> 11, s = mm & 2047;
                    if (blockIdx.z == 2) {
                        __half* vtb = &g_vt[(((size_t)bb_ * H + h) * DK + dk) * S + s];
                        vtb[0] = __float2half_rn(vx);
                        vtb[S] = __float2half_rn(vy);
                    } else {
                        __half* orow = (blockIdx.z == 0 ? g_qh : g_kh)
                                       + (((size_t)bb_ * H + h) * S + s) * DK;
                        *(__half2*)&orow[dk] = __floats2half2_rn(vx, vy);
                    }
                } else {
                    const float* rr = resid + (size_t)mm * D + n;
                    float2 r2 = *(const float2*)rr;
                    float2* p = (float2*)&O1f[(size_t)mm * D + n];
                    *p = make_float2(vx + r2.x, vy + r2.y);
                }
            }
        }
    }
}

// ---------------------------------------------------------------------------
// K2: attention via fp16 mma.sync m16n8k16 + ldmatrix fragment loads.
// E written fp16 to g_eh scratch; ctx written fp16 to g_ctx.
// grid (16 q-tiles, 64 bh), block 256. Warp grid 4x2.
// ---------------------------------------------------------------------------
__global__ __launch_bounds__(256, 2) void attn_mma_kernel()
{
    extern __shared__ uint32_t smu[];
    uint32_t* Ps = smu + AP_OFF;
    float* rs    = (float*)(smu + ARS_OFF);
    float* sinv  = (float*)(smu + AIV_OFF);
    const uint32_t smem_u = smem_to_u32(smu);
    const uint32_t qs_u = smem_u + AQ_OFF * 4;
    const uint32_t ks_u = smem_u + AK_OFF * 4;
    const uint32_t vt_u = smem_u + AV_OFF * 4;
    const uint32_t ps_u = smem_u + AP_OFF * 4;

    const int bh = blockIdx.y;
    const int q0 = blockIdx.x * 128;
    const int tid = threadIdx.x;
    const int wid = tid >> 5, lane = tid & 31;
    const int g = lane >> 2, tq = lane & 3;
    const int wm = (wid >> 1) * 32;
    const int wn = (wid & 1) * 32;

    // ldmatrix per-lane address components (stride AST)
    const int mat  = lane >> 3;
    const int lrow = lane & 7;
    const int matb = (lane >> 3) & 1;
    const uint32_t aoff =
        ((uint32_t)((wm + (mat & 1) * 8 + lrow) * AST + (mat >> 1) * 4)) * 4;
    const uint32_t boff =
        ((uint32_t)((wn + lrow) * AST + matb * 4)) * 4;

    // prologue: Q + K(0) in one group, V(0) in a second group
#pragma unroll
    for (int i = 0; i < 4; i++) {
        int idx = tid + i * 256;
        int row = idx >> 3, ch = idx & 7;
        cp16(qs_u + (uint32_t)(row * AST + ch * 4) * 4,
             &g_qh[((size_t)bh * S + q0 + row) * DK + ch * 8]);
    }
#pragma unroll
    for (int i = 0; i < 2; i++) {
        int idx = tid + i * 256;
        int row = idx >> 3, ch = idx & 7;
        cp16(ks_u + (uint32_t)(row * AST + ch * 4) * 4,
             &g_kh[((size_t)bh * S + row) * DK + ch * 8]);
    }
    cp_commit();
#pragma unroll
    for (int i = 0; i < 2; i++) {
        int idx = tid + i * 256;
        int row = idx >> 3, ch = idx & 7;
        cp16(vt_u + (uint32_t)(row * AST + ch * 4) * 4,
             &g_vt[((size_t)bh * DK + row) * S + ch * 8]);
    }
    cp_commit();

    float cacc[2][4][4];
    float rsum[2][2] = {{0.f, 0.f}, {0.f, 0.f}};
#pragma unroll
    for (int mf = 0; mf < 2; mf++)
#pragma unroll
        for (int nf = 0; nf < 4; nf++)
#pragma unroll
            for (int r = 0; r < 4; r++) cacc[mf][nf][r] = 0.f;

    for (int kt = 0; kt < S / 64; kt++) {
        const int k0 = kt * 64;

        cp_wait1();            // Q + K(kt) arrived (V may be in flight)
        __syncthreads();

        // S = Q·K^T  (k = d = 64 -> 4 fp16 k16 steps); ldmatrix frags
        float sacc[2][4][4];
#pragma unroll
        for (int mf = 0; mf < 2; mf++)
#pragma unroll
            for (int nf = 0; nf < 4; nf++)
#pragma unroll
                for (int r = 0; r < 4; r++) sacc[mf][nf][r] = 0.f;
#pragma unroll
        for (int ks = 0; ks < 4; ks++) {
            const int kk = ks * 8;      // word offset (16 halfs)
            uint32_t a[2][4], b[4][2];
#pragma unroll
            for (int mf = 0; mf < 2; mf++)
                ldsm_x4(a[mf], qs_u + aoff + (uint32_t)(mf * 16 * AST + kk) * 4);
#pragma unroll
            for (int nf = 0; nf < 4; nf++)
                ldsm_x2(b[nf], ks_u + boff + (uint32_t)(nf * 8 * AST + kk) * 4);
#pragma unroll
            for (int mf = 0; mf < 2; mf++)
#pragma unroll
                for (int nf = 0; nf < 4; nf++)
                    mma_f16(sacc[mf][nf], a[mf], b[nf]);
        }

        // exp, rowsum, E -> g_eh (fp16 unnormalized), P -> smem (fp16)
#pragma unroll
        for (int mf = 0; mf < 2; mf++) {
            const int r0 = wm + mf * 16 + g;
#pragma unroll
            for (int nf = 0; nf < 4; nf++) {
                const int c0 = wn + nf * 8 + tq * 2;
                float e00 = fast_exp(sacc[mf][nf][0]);
                float e01 = fast_exp(sacc[mf][nf][1]);
                float e10 = fast_exp(sacc[mf][nf][2]);
                float e11 = fast_exp(sacc[mf][nf][3]);
                rsum[mf][0] += e00 + e01;
                rsum[mf][1] += e10 + e11;
                uint32_t p01 = h2u(__floats2half2_rn(e00, e01));
                uint32_t p23 = h2u(__floats2half2_rn(e10, e11));
                *(uint32_t*)&g_eh[((size_t)bh * S + q0 + r0) * S + k0 + c0] = p01;
                *(uint32_t*)&g_eh[((size_t)bh * S + q0 + r0 + 8) * S + k0 + c0] = p23;
                Ps[r0 * AST + (c0 >> 1)]       = p01;
                Ps[(r0 + 8) * AST + (c0 >> 1)] = p23;
            }
        }

        cp_wait0();            // V(kt) arrived
        __syncthreads();       // publish V + Ps; Ks fully consumed

        // issue K(kt+1) — overlaps the P·V phase below
        if (kt + 1 < S / 64) {
            const int nk0 = k0 + 64;
#pragma unroll
            for (int i = 0; i < 2; i++) {
                int idx = tid + i * 256;
                int row = idx >> 3, ch = idx & 7;
                cp16(ks_u + (uint32_t)(row * AST + ch * 4) * 4,
                     &g_kh[((size_t)bh * S + nk0 + row) * DK + ch * 8]);
            }
            cp_commit();
        }

        // ctx += P·V (k = keys = 64 -> 4 fp16 k16 steps); ldmatrix frags
#pragma unroll
        for (int ks = 0; ks < 4; ks++) {
            const int kk = ks * 8;
            uint32_t a[2][4], b[4][2];
#pragma unroll
            for (int mf = 0; mf < 2; mf++)
                ldsm_x4(a[mf], ps_u + aoff + (uint32_t)(mf * 16 * AST + kk) * 4);
#pragma unroll
            for (int nf = 0; nf < 4; nf++)
                ldsm_x2(b[nf], vt_u + boff + (uint32_t)(nf * 8 * AST + kk) * 4);
#pragma unroll
            for (int mf = 0; mf < 2; mf++)
#pragma unroll
                for (int nf = 0; nf < 4; nf++)
                    mma_f16(cacc[mf][nf], a[mf], b[nf]);
        }
        __syncthreads();       // Vt + Ps fully consumed

        // issue V(kt+1) — overlaps the next tile's QK phase
        if (kt + 1 < S / 64) {
            const int nk0 = k0 + 64;
#pragma unroll
            for (int i = 0; i < 2; i++) {
                int idx = tid + i * 256;
                int row = idx >> 3, ch = idx & 7;
                cp16(vt_u + (uint32_t)(row * AST + ch * 4) * 4,
                     &g_vt[((size_t)bh * DK + row) * S + nk0 + ch * 8]);
            }
            cp_commit();
        }
    }

    // rowsum: reduce across tq lanes (same g), publish per warp-column
#pragma unroll
    for (int mf = 0; mf < 2; mf++)
#pragma unroll
        for (int hh = 0; hh < 2; hh++) {
            float v = rsum[mf][hh];
            v += __shfl_xor_sync(0xffffffffu, v, 1);
            v += __shfl_xor_sync(0xffffffffu, v, 2);
            rsum[mf][hh] = v;
        }
    if (tq == 0) {
#pragma unroll
        for (int mf = 0; mf < 2; mf++)
#pragma unroll
            for (int hh = 0; hh < 2; hh++)
                rs[(wid & 1) * 128 + wm + mf * 16 + hh * 8 + g] = rsum[mf][hh];
    }
    __syncthreads();
    if (tid < 128) {
        float iv = 1.0f / (rs[tid] + rs[128 + tid]);
        g_rinv[(size_t)bh * S + q0 + tid] = iv;
        sinv[tid] = iv;
    }
    __syncthreads();

    // scaled ctx -> g_ctx (fp16: consumed only by fc's fp16 MMA)
    const int b_ = bh >> 4, h_ = bh & 15;
#pragma unroll
    for (int mf = 0; mf < 2; mf++) {
        const int r0 = wm + mf * 16 + g;
        const float iv0 = sinv[r0], iv1 = sinv[r0 + 8];
#pragma unroll
        for (int nf = 0; nf < 4; nf++) {
            const int c0 = wn + nf * 8 + tq * 2;
            *(__half2*)&g_ctx[((size_t)b_ * S + q0 + r0) * D + h_ * DK + c0] =
                __floats2half2_rn(cacc[mf][nf][0] * iv0, cacc[mf][nf][1] * iv0);
            *(__half2*)&g_ctx[((size_t)b_ * S + q0 + r0 + 8) * D + h_ * DK + c0] =
                __floats2half2_rn(cacc[mf][nf][2] * iv1, cacc[mf][nf][3] * iv1);
        }
    }
}

// ---------------------------------------------------------------------------
// K3: normalize: attn_out[row][*] = half2float(g_eh[row][*]) * rinv[row]
// ---------------------------------------------------------------------------
__global__ __launch_bounds__(256) void attn_scale_kernel(float* __restrict__ attn)
{
    size_t idx4 = (size_t)blockIdx.x * blockDim.x + threadIdx.x;  // 4-elem idx
    size_t row  = idx4 >> 9;                                      // 512 groups/row
    float inv = g_rinv[row];
    uint2 e = __ldcs((const uint2*)g_eh + idx4);
    __half2 h0, h1;
    __builtin_memcpy(&h0, &e.x, 4);
    __builtin_memcpy(&h1, &e.y, 4);
    float2 f0 = __half22float2(h0);
    float2 f1 = __half22float2(h1);
    float4 v = make_float4(f0.x * inv, f0.y * inv, f1.x * inv, f1.y * inv);
    __stcs((float4*)attn + idx4, v);
}

// ---------------------------------------------------------------------------
// K5: LayerNorm over last dim (1024). One block (256 thr) per row.
// ---------------------------------------------------------------------------
__global__ __launch_bounds__(256) void ln_kernel(
    const float* __restrict__ gamma, const float* __restrict__ beta,
    float* __restrict__ out)
{
    __shared__ float s1[8], s2[8];
    __shared__ float sm_mean, sm_rstd;
    const int row = blockIdx.x;
    const int t   = threadIdx.x;
    const float* x = g_x + (size_t)row * D;

    float4 v = *(const float4*)(x + t * 4);
    float sum = v.x + v.y + v.z + v.w;
    float sq  = v.x * v.x + v.y * v.y + v.z * v.z + v.w * v.w;
#pragma unroll
    for (int m = 16; m >= 1; m >>= 1) {
        sum += __shfl_xor_sync(0xffffffffu, sum, m);
        sq  += __shfl_xor_sync(0xffffffffu, sq, m);
    }
    const int warp = t >> 5, lane = t & 31;
    if (lane == 0) { s1[warp] = sum; s2[warp] = sq; }
    __syncthreads();
    if (t == 0) {
        float a = 0.f, c = 0.f;
#pragma unroll
        for (int w = 0; w < 8; w++) { a += s1[w]; c += s2[w]; }
        float mean = a * (1.0f / D);
        float var  = c * (1.0f / D) - mean * mean;
        sm_mean = mean;
        sm_rstd = rsqrtf(var + 1e-6f);
    }
    __syncthreads();
    const float mean = sm_mean, r = sm_rstd;
    float4 g4 = *(const float4*)(gamma + t * 4);
    float4 b4 = *(const float4*)(beta + t * 4);
    float4 o;
    o.x = (v.x - mean) * r * g4.x + b4.x;
    o.y = (v.y - mean) * r * g4.y + b4.y;
    o.z = (v.z - mean) * r * g4.z + b4.z;
    o.w = (v.w - mean) * r * g4.w + b4.w;
    *(float4*)(out + (size_t)row * D + t * 4) = o;
}

// ---------------------------------------------------------------------------
extern "C" void kernel_launch(void* const* d_in, const int* in_sizes, int n_in,
                              void* d_out, int out_size)
{
    const float* q     = (const float*)d_in[0];
    const float* k     = (const float*)d_in[1];
    const float* v     = (const float*)d_in[2];
    const float* Wq    = (const float*)d_in[3];
    const float* bq    = (const float*)d_in[4];
    const float* Wfc   = (const float*)d_in[5];
    const float* bfc   = (const float*)d_in[6];
    const float* gamma = (const float*)d_in[7];
    const float* beta  = (const float*)d_in[8];

    float* out_x    = (float*)d_out;
    float* out_attn = out_x + X_ELEMS;

    cudaFuncSetAttribute(gemm_f16_kernel,
                         cudaFuncAttributeMaxDynamicSharedMemorySize, GEMM_SMEM);
    cudaFuncSetAttribute(attn_mma_kernel,
                         cudaFuncAttributeMaxDynamicSharedMemorySize, ATTN_SMEM);

    __half *qcv_p, *kcv_p, *vcv_p, *wqt_p, *wfct_p, *ctx_p;
    float *x_p;
    cudaGetSymbolAddress((void**)&qcv_p,  g_qcv);
    cudaGetSymbolAddress((void**)&kcv_p,  g_kcv);
    cudaGetSymbolAddress((void**)&vcv_p,  g_vcv);
    cudaGetSymbolAddress((void**)&wqt_p,  g_wqt);
    cudaGetSymbolAddress((void**)&wfct_p, g_wfct);
    cudaGetSymbolAddress((void**)&ctx_p,  g_ctx);
    cudaGetSymbolAddress((void**)&x_p,    g_x);

    convert_kernel<<<dim3((unsigned)(X_ELEMS / 4 / 256), 3), 256>>>(q, k, v);
    transpose_kernel<<<dim3(32, 32, 2), dim3(32, 8)>>>(Wq, Wfc);
    gemm_f16_kernel<<<dim3(8, 64, 3), 256, GEMM_SMEM>>>(
        qcv_p, kcv_p, vcv_p, wqt_p, bq, nullptr, nullptr, 0);
    attn_mma_kernel<<<dim3(16, 64), 256, ATTN_SMEM>>>();
    attn_scale_kernel<<<(unsigned)(ATTN_ELEMS / 4 / 256), 256>>>(out_attn);
    gemm_f16_kernel<<<dim3(8, 64, 1), 256, GEMM_SMEM>>>(
        ctx_p, ctx_p, ctx_p, wfct_p, bfc, q, x_p, 1);
    ln_kernel<<<B * S, 256>>>(gamma, beta, out_x);
}

// round 14
// speedup vs baseline: 1.9115x; 1.0661x over previous
#include <cuda_runtime.h>
#include <cuda_fp16.h>
#include <cstdint>

// ---------------------------------------------------------------------------
// MultiHeadAttention (B=4, S=2048, D=1024, H=16, DK=64).
// Round 14: R13 + coalesced E-writeback. The exp phase no longer issues
// scattered scalar STG; after the P·V phase each CTA copies Ps (smem,
// already holding fp16 E) to g_eh with uint4 stores (full 128B rows).
// Output layout: d_out = [ x (8,388,608 f32) | attn (268,435,456 f32) ]
// ---------------------------------------------------------------------------

namespace {
constexpr int B  = 4;
constexpr int S  = 2048;
constexpr int D  = 1024;
constexpr int H  = 16;
constexpr int DK = 64;
constexpr size_t QH_ELEMS   = (size_t)B * H * S * DK;        // 8,388,608
constexpr size_t X_ELEMS    = (size_t)B * S * D;             // 8,388,608
constexpr size_t ATTN_ELEMS = (size_t)B * H * S * (size_t)S; // 268,435,456

// fp16 dense-GEMM tiling: CTA 128x128, warp 64x32 (2x4 warps),
// K-chunk 32 halfs (2 k16 steps), two cp.async stages.
constexpr int KC  = 32;                     // halfs per chunk
constexpr int NCH = D / KC;                 // 32 chunks
constexpr int GST = 20;                     // words/row; 8-row ldmatrix conflict-free
constexpr int GTILE = 128 * GST;            // words per tile (2560)
constexpr int GEMM_SMEM = 4 * GTILE * 4;    // 40,960 B

// attention smem (32-bit words), R11/R12-proven.
constexpr int AST = 36;
constexpr int AQ_OFF = 0;                   // Qs[128][36w] fp16, pre-scaled
constexpr int AK_OFF = AQ_OFF + 128 * AST;  // Ks[64][36w]  fp16
constexpr int AV_OFF = AK_OFF + 64 * AST;   // Vt[64][36w]  fp16 (d rows, key cols)
constexpr int AP_OFF = AV_OFF + 64 * AST;   // Ps[128][36w] fp16
constexpr int ARS_OFF = AP_OFF + 128 * AST; // rs[2][128] floats
constexpr int AIV_OFF = ARS_OFF + 256;      // sinv[128] floats
constexpr int ATTN_SMEM = (AIV_OFF + 128) * 4;   // 56,832 B
}

// Scratch (allocation-free rule: __device__ globals)
__device__ __half g_qcv[X_ELEMS];          // fp16 copies of inputs
__device__ __half g_kcv[X_ELEMS];
__device__ __half g_vcv[X_ELEMS];
__device__ __half g_qh[QH_ELEMS];          // fp16, pre-scaled by 0.125
__device__ __half g_kh[QH_ELEMS];          // fp16
__device__ __half g_vt[QH_ELEMS];          // fp16; V transposed [bh][d][s]
__device__ __half g_ctx[X_ELEMS];          // fp16 (consumed by fc MMA)
__device__ __half g_eh[ATTN_ELEMS];        // fp16 unnormalized exp(S) scratch
__device__ float  g_x[X_ELEMS];            // fp32
__device__ float  g_rinv[(size_t)B * H * S];
__device__ __half g_wqt[(size_t)D * D];    // Wq^T  [N][K] fp16
__device__ __half g_wfct[(size_t)D * D];   // Wfc^T [N][K] fp16

// ---------------------------------------------------------------------------
// helpers
// ---------------------------------------------------------------------------
__device__ __forceinline__ uint32_t smem_to_u32(const void* p) {
    uint32_t a;
    asm("{ .reg .u64 t; cvta.to.shared.u64 t, %1; cvt.u32.u64 %0, t; }"
        : "=r"(a) : "l"(p));
    return a;
}
__device__ __forceinline__ uint32_t h2u(__half2 h) {
    uint32_t u;
    __builtin_memcpy(&u, &h, 4);
    return u;
}
__device__ __forceinline__ void mma_f16(float* d, const uint32_t* a, const uint32_t* b) {
    asm volatile(
        "mma.sync.aligned.m16n8k16.row.col.f32.f16.f16.f32 "
        "{%0,%1,%2,%3}, {%4,%5,%6,%7}, {%8,%9}, {%0,%1,%2,%3};"
        : "+f"(d[0]), "+f"(d[1]), "+f"(d[2]), "+f"(d[3])
        : "r"(a[0]), "r"(a[1]), "r"(a[2]), "r"(a[3]), "r"(b[0]), "r"(b[1]));
}
__device__ __forceinline__ void ldsm_x4(uint32_t* r, uint32_t addr) {
    asm volatile("ldmatrix.sync.aligned.m8n8.x4.shared.b16 {%0,%1,%2,%3}, [%4];"
        : "=r"(r[0]), "=r"(r[1]), "=r"(r[2]), "=r"(r[3]) : "r"(addr));
}
__device__ __forceinline__ void ldsm_x2(uint32_t* r, uint32_t addr) {
    asm volatile("ldmatrix.sync.aligned.m8n8.x2.shared.b16 {%0,%1}, [%2];"
        : "=r"(r[0]), "=r"(r[1]) : "r"(addr));
}
__device__ __forceinline__ void cp16(uint32_t dst, const void* src) {
    asm volatile("cp.async.cg.shared.global [%0], [%1], 16;" :: "r"(dst), "l"(src));
}
__device__ __forceinline__ void cp_commit() {
    asm volatile("cp.async.commit_group;" ::: "memory");
}
__device__ __forceinline__ void cp_wait0() {
    asm volatile("cp.async.wait_group 0;" ::: "memory");
}
__device__ __forceinline__ void cp_wait1() {
    asm volatile("cp.async.wait_group 1;" ::: "memory");
}
// exp via FMA pipe: magic-number range reduction + deg-5 poly (rel err ~2e-6).
__device__ __forceinline__ float fast_exp(float x) {
    const float L2E = 1.4426950408889634f;
    float t = fmaf(x, L2E, 12582912.0f);
    float n = t - 12582912.0f;
    float f = fmaf(x, L2E, -n);
    float p = 0.0013333558f;
    p = fmaf(p, f, 0.0096181291f);
    p = fmaf(p, f, 0.0555041087f);
    p = fmaf(p, f, 0.2402265069f);
    p = fmaf(p, f, 0.6931471806f);
    p = fmaf(p, f, 1.0f);
    return __int_as_float(__float_as_int(p) + (__float_as_int(t) << 23));
}

// ---------------------------------------------------------------------------
// K0a: convert q,k,v (fp32) -> fp16 gmem. blockIdx.y selects tensor.
// ---------------------------------------------------------------------------
__global__ __launch_bounds__(256) void convert_kernel(
    const float* __restrict__ q, const float* __restrict__ k,
    const float* __restrict__ v)
{
    const float* src = (blockIdx.y == 0) ? q : (blockIdx.y == 1) ? k : v;
    __half* dst = (blockIdx.y == 0) ? g_qcv : (blockIdx.y == 1) ? g_kcv : g_vcv;
    size_t i4 = (size_t)blockIdx.x * blockDim.x + threadIdx.x;   // float4 idx
    float4 fv = *((const float4*)src + i4);
    __half2 h0 = __floats2half2_rn(fv.x, fv.y);
    __half2 h1 = __floats2half2_rn(fv.z, fv.w);
    uint2 o = make_uint2(h2u(h0), h2u(h1));
    *((uint2*)dst + i4) = o;
}

// ---------------------------------------------------------------------------
// K0b: transpose Wq and Wfc once -> g_wqt / g_wfct (fp16 at store)
// ---------------------------------------------------------------------------
__global__ __launch_bounds__(256) void transpose_kernel(
    const float* __restrict__ Wq, const float* __restrict__ Wfc)
{
    __shared__ float tile[32][33];
    const float* src = blockIdx.z ? Wfc : Wq;
    __half*      dst = blockIdx.z ? g_wfct : g_wqt;
    int x = blockIdx.x * 32 + threadIdx.x;
    int y = blockIdx.y * 32 + threadIdx.y;
#pragma unroll
    for (int i = 0; i < 32; i += 8)
        tile[threadIdx.y + i][threadIdx.x] = src[(size_t)(y + i) * D + x];
    __syncthreads();
    int tx = blockIdx.y * 32 + threadIdx.x;
    int ty = blockIdx.x * 32 + threadIdx.y;
#pragma unroll
    for (int i = 0; i < 32; i += 8)
        dst[(size_t)(ty + i) * D + tx] =
            __float2half_rn(tile[threadIdx.x][threadIdx.y + i]);
}

// ---------------------------------------------------------------------------
// K1/K4: fp16 mma.sync GEMM, 2-stage cp.async pipeline, ldmatrix frags.
// Y[m,n] = A[m,:] . Bt[n,:]  (+bias[, +resid])
// mode 0: proj -> fp16 outputs (z=0 qh scaled by 0.125, z=1 kh, z=2 Vt).
// mode 1: fc (A = g_ctx fp16, B = Wfc^T fp16) -> fp32 g_x + resid.
// ---------------------------------------------------------------------------
__global__ __launch_bounds__(256) void gemm_f16_kernel(
    const __half* __restrict__ A0, const __half* __restrict__ A1,
    const __half* __restrict__ A2, const __half* __restrict__ Bt,
    const float* __restrict__ bias, const float* __restrict__ resid,
    float* __restrict__ O1f, int mode)
{
    extern __shared__ uint32_t smu[];
    const uint32_t smem_u = smem_to_u32(smu);

    const int tid  = threadIdx.x;
    const int wid  = tid >> 5, lane = tid & 31;
    const int g    = lane >> 2, tq = lane & 3;
    const int wm   = (wid >> 2) * 64;
    const int wn   = (wid & 3) * 32;
    const int n0   = blockIdx.x * 128;
    const int m0   = blockIdx.y * 128;

    // ldmatrix per-lane address components
    const int mat  = lane >> 3;           // 0..3 (A x4 groups)
    const int lrow = lane & 7;
    const int matb = (lane >> 3) & 1;     // B x2 groups
    const uint32_t aoff =
        ((uint32_t)((wm + (mat & 1) * 8 + lrow) * GST + (mat >> 1) * 4)) * 4;
    const uint32_t boff =
        ((uint32_t)((wn + lrow) * GST + matb * 4)) * 4;

    const __half* Ap;
    if (blockIdx.z == 0)      Ap = A0;
    else if (blockIdx.z == 1) Ap = A1;
    else                      Ap = A2;

    float acc[4][4][4];
#pragma unroll
    for (int i = 0; i < 4; i++)
#pragma unroll
        for (int j = 0; j < 4; j++)
#pragma unroll
            for (int r = 0; r < 4; r++) acc[i][j][r] = 0.f;

    // prologue: issue chunks 0 (stage 0) and 1 (stage 1)
#pragma unroll
    for (int c0 = 0; c0 < 2; c0++) {
        const int kt = c0 * KC;
        const uint32_t sbase = smem_u + (uint32_t)(c0 * 2 * GTILE) * 4;
#pragma unroll
        for (int j = 0; j < 2; j++) {
            int idx = tid + j * 256;
            int row = idx >> 2, ch = idx & 3;
            uint32_t off = (uint32_t)(row * GST + ch * 4) * 4;
            cp16(sbase + off,             Ap + (size_t)(m0 + row) * D + kt + ch * 8);
            cp16(sbase + off + GTILE * 4, Bt + (size_t)(n0 + row) * D + kt + ch * 8);
        }
        cp_commit();
    }

    for (int c = 0; c < NCH; c++) {
        const int st = c & 1;
        if (c + 1 < NCH) cp_wait1(); else cp_wait0();
        __syncthreads();

        const uint32_t abase = smem_u + (uint32_t)(st * 2 * GTILE) * 4 + aoff;
        const uint32_t bbase = smem_u + (uint32_t)(st * 2 * GTILE + GTILE) * 4 + boff;

#pragma unroll
        for (int ks = 0; ks < 2; ks++) {       // 2 k16 steps per 32-half chunk
            const int kk = ks * 8;             // word offset
            uint32_t a[4][4], b[4][2];
#pragma unroll
            for (int mf = 0; mf < 4; mf++)
                ldsm_x4(a[mf], abase + (uint32_t)(mf * 16 * GST + kk) * 4);
#pragma unroll
            for (int nf = 0; nf < 4; nf++)
                ldsm_x2(b[nf], bbase + (uint32_t)(nf * 8 * GST + kk) * 4);
#pragma unroll
            for (int mf = 0; mf < 4; mf++)
#pragma unroll
                for (int nf = 0; nf < 4; nf++)
                    mma_f16(acc[mf][nf], a[mf], b[nf]);
        }
        __syncthreads();

        // refill this stage with chunk c+2 (overlaps chunk c+1's compute)
        if (c + 2 < NCH) {
            const int kt = (c + 2) * KC;
            const uint32_t sbase = smem_u + (uint32_t)(st * 2 * GTILE) * 4;
#pragma unroll
            for (int j = 0; j < 2; j++) {
                int idx = tid + j * 256;
                int row = idx >> 2, ch = idx & 3;
                uint32_t off = (uint32_t)(row * GST + ch * 4) * 4;
                cp16(sbase + off,             Ap + (size_t)(m0 + row) * D + kt + ch * 8);
                cp16(sbase + off + GTILE * 4, Bt + (size_t)(n0 + row) * D + kt + ch * 8);
            }
            cp_commit();
        }
    }

    const float osc = (blockIdx.z == 0 && mode == 0) ? 0.125f : 1.0f;

#pragma unroll
    for (int mf = 0; mf < 4; mf++) {
#pragma unroll
        for (int nf = 0; nf < 4; nf++) {
            const int m = m0 + wm + mf * 16 + g;
            const int n = n0 + wn + nf * 8 + tq * 2;
            float bx = bias[n], by = bias[n + 1];
#pragma unroll
            for (int half = 0; half < 2; half++) {
                const int mm = m + half * 8;
                float vx = acc[mf][nf][half * 2 + 0] + bx;
                float vy = acc[mf][nf][half * 2 + 1] + by;
                if (mode == 0) {
                    vx *= osc; vy *= osc;
                    const int h = n >> 6, dk = n & 63;
                    const int bb_ = mm >> 11, s = mm & 2047;
                    if (blockIdx.z == 2) {
                        __half* vtb = &g_vt[(((size_t)bb_ * H + h) * DK + dk) * S + s];
                        vtb[0] = __float2half_rn(vx);
                        vtb[S] = __float2half_rn(vy);
                    } else {
                        __half* orow = (blockIdx.z == 0 ? g_qh : g_kh)
                                       + (((size_t)bb_ * H + h) * S + s) * DK;
                        *(__half2*)&orow[dk] = __floats2half2_rn(vx, vy);
                    }
                } else {
                    const float* rr = resid + (size_t)mm * D + n;
                    float2 r2 = *(const float2*)rr;
                    float2* p = (float2*)&O1f[(size_t)mm * D + n];
                    *p = make_float2(vx + r2.x, vy + r2.y);
                }
            }
        }
    }
}

// ---------------------------------------------------------------------------
// K2: attention via fp16 mma.sync m16n8k16 + ldmatrix fragment loads.
// exp phase writes Ps (smem) only; after P·V the CTA copies Ps -> g_eh
// with coalesced uint4 stores (full 128B rows). ctx -> fp16 g_ctx.
// grid (16 q-tiles, 64 bh), block 256. Warp grid 4x2.
// ---------------------------------------------------------------------------
__global__ __launch_bounds__(256, 2) void attn_mma_kernel()
{
    extern __shared__ uint32_t smu[];
    uint32_t* Ps = smu + AP_OFF;
    float* rs    = (float*)(smu + ARS_OFF);
    float* sinv  = (float*)(smu + AIV_OFF);
    const uint32_t smem_u = smem_to_u32(smu);
    const uint32_t qs_u = smem_u + AQ_OFF * 4;
    const uint32_t ks_u = smem_u + AK_OFF * 4;
    const uint32_t vt_u = smem_u + AV_OFF * 4;
    const uint32_t ps_u = smem_u + AP_OFF * 4;

    const int bh = blockIdx.y;
    const int q0 = blockIdx.x * 128;
    const int tid = threadIdx.x;
    const int wid = tid >> 5, lane = tid & 31;
    const int g = lane >> 2, tq = lane & 3;
    const int wm = (wid >> 1) * 32;
    const int wn = (wid & 1) * 32;

    // ldmatrix per-lane address components (stride AST)
    const int mat  = lane >> 3;
    const int lrow = lane & 7;
    const int matb = (lane >> 3) & 1;
    const uint32_t aoff =
        ((uint32_t)((wm + (mat & 1) * 8 + lrow) * AST + (mat >> 1) * 4)) * 4;
    const uint32_t boff =
        ((uint32_t)((wn + lrow) * AST + matb * 4)) * 4;

    // prologue: Q + K(0) in one group, V(0) in a second group
#pragma unroll
    for (int i = 0; i < 4; i++) {
        int idx = tid + i * 256;
        int row = idx >> 3, ch = idx & 7;
        cp16(qs_u + (uint32_t)(row * AST + ch * 4) * 4,
             &g_qh[((size_t)bh * S + q0 + row) * DK + ch * 8]);
    }
#pragma unroll
    for (int i = 0; i < 2; i++) {
        int idx = tid + i * 256;
        int row = idx >> 3, ch = idx & 7;
        cp16(ks_u + (uint32_t)(row * AST + ch * 4) * 4,
             &g_kh[((size_t)bh * S + row) * DK + ch * 8]);
    }
    cp_commit();
#pragma unroll
    for (int i = 0; i < 2; i++) {
        int idx = tid + i * 256;
        int row = idx >> 3, ch = idx & 7;
        cp16(vt_u + (uint32_t)(row * AST + ch * 4) * 4,
             &g_vt[((size_t)bh * DK + row) * S + ch * 8]);
    }
    cp_commit();

    float cacc[2][4][4];
    float rsum[2][2] = {{0.f, 0.f}, {0.f, 0.f}};
#pragma unroll
    for (int mf = 0; mf < 2; mf++)
#pragma unroll
        for (int nf = 0; nf < 4; nf++)
#pragma unroll
            for (int r = 0; r < 4; r++) cacc[mf][nf][r] = 0.f;

    for (int kt = 0; kt < S / 64; kt++) {
        const int k0 = kt * 64;

        cp_wait1();            // Q + K(kt) arrived (V may be in flight)
        __syncthreads();

        // S = Q·K^T  (k = d = 64 -> 4 fp16 k16 steps); ldmatrix frags
        float sacc[2][4][4];
#pragma unroll
        for (int mf = 0; mf < 2; mf++)
#pragma unroll
            for (int nf = 0; nf < 4; nf++)
#pragma unroll
                for (int r = 0; r < 4; r++) sacc[mf][nf][r] = 0.f;
#pragma unroll
        for (int ks = 0; ks < 4; ks++) {
            const int kk = ks * 8;      // word offset (16 halfs)
            uint32_t a[2][4], b[4][2];
#pragma unroll
            for (int mf = 0; mf < 2; mf++)
                ldsm_x4(a[mf], qs_u + aoff + (uint32_t)(mf * 16 * AST + kk) * 4);
#pragma unroll
            for (int nf = 0; nf < 4; nf++)
                ldsm_x2(b[nf], ks_u + boff + (uint32_t)(nf * 8 * AST + kk) * 4);
#pragma unroll
            for (int mf = 0; mf < 2; mf++)
#pragma unroll
                for (int nf = 0; nf < 4; nf++)
                    mma_f16(sacc[mf][nf], a[mf], b[nf]);
        }

        // exp, rowsum, P -> smem (fp16). E-writeback happens coalesced below.
#pragma unroll
        for (int mf = 0; mf < 2; mf++) {
            const int r0 = wm + mf * 16 + g;
#pragma unroll
            for (int nf = 0; nf < 4; nf++) {
                const int c0 = wn + nf * 8 + tq * 2;
                float e00 = fast_exp(sacc[mf][nf][0]);
                float e01 = fast_exp(sacc[mf][nf][1]);
                float e10 = fast_exp(sacc[mf][nf][2]);
                float e11 = fast_exp(sacc[mf][nf][3]);
                rsum[mf][0] += e00 + e01;
                rsum[mf][1] += e10 + e11;
                Ps[r0 * AST + (c0 >> 1)]       = h2u(__floats2half2_rn(e00, e01));
                Ps[(r0 + 8) * AST + (c0 >> 1)] = h2u(__floats2half2_rn(e10, e11));
            }
        }

        cp_wait0();            // V(kt) arrived
        __syncthreads();       // publish V + Ps; Ks fully consumed

        // issue K(kt+1) — overlaps the P·V phase below
        if (kt + 1 < S / 64) {
            const int nk0 = k0 + 64;
#pragma unroll
            for (int i = 0; i < 2; i++) {
                int idx = tid + i * 256;
                int row = idx >> 3, ch = idx & 7;
                cp16(ks_u + (uint32_t)(row * AST + ch * 4) * 4,
                     &g_kh[((size_t)bh * S + nk0 + row) * DK + ch * 8]);
            }
            cp_commit();
        }

        // ctx += P·V (k = keys = 64 -> 4 fp16 k16 steps); ldmatrix frags
#pragma unroll
        for (int ks = 0; ks < 4; ks++) {
            const int kk = ks * 8;
            uint32_t a[2][4], b[4][2];
#pragma unroll
            for (int mf = 0; mf < 2; mf++)
                ldsm_x4(a[mf], ps_u + aoff + (uint32_t)(mf * 16 * AST + kk) * 4);
#pragma unroll
            for (int nf = 0; nf < 4; nf++)
                ldsm_x2(b[nf], vt_u + boff + (uint32_t)(nf * 8 * AST + kk) * 4);
#pragma unroll
            for (int mf = 0; mf < 2; mf++)
#pragma unroll
                for (int nf = 0; nf < 4; nf++)
                    mma_f16(cacc[mf][nf], a[mf], b[nf]);
        }

        // coalesced E writeback: Ps -> g_eh tile block (128 rows x 64 halfs).
        // Each warp STG.128 covers 4 complete 128B rows (bit-identical data).
        {
            __half* ebase = &g_eh[((size_t)bh * S + q0) * S + k0];
#pragma unroll
            for (int i = 0; i < 4; i++) {
                int idx = tid + i * 256;
                int row = idx >> 3, c4 = idx & 7;
                uint4 val = *(const uint4*)&Ps[row * AST + c4 * 4];
                *(uint4*)(ebase + (size_t)row * S + c4 * 8) = val;
            }
        }
        __syncthreads();       // Vt + Ps fully consumed

        // issue V(kt+1) — overlaps the next tile's QK phase
        if (kt + 1 < S / 64) {
            const int nk0 = k0 + 64;
#pragma unroll
            for (int i = 0; i < 2; i++) {
                int idx = tid + i * 256;
                int row = idx >> 3, ch = idx & 7;
                cp16(vt_u + (uint32_t)(row * AST + ch * 4) * 4,
                     &g_vt[((size_t)bh * DK + row) * S + nk0 + ch * 8]);
            }
            cp_commit();
        }
    }

    // rowsum: reduce across tq lanes (same g), publish per warp-column
#pragma unroll
    for (int mf = 0; mf < 2; mf++)
#pragma unroll
        for (int hh = 0; hh < 2; hh++) {
            float v = rsum[mf][hh];
            v += __shfl_xor_sync(0xffffffffu, v, 1);
            v += __shfl_xor_sync(0xffffffffu, v, 2);
            rsum[mf][hh] = v;
        }
    if (tq == 0) {
#pragma unroll
        for (int mf = 0; mf < 2; mf++)
#pragma unroll
            for (int hh = 0; hh < 2; hh++)
                rs[(wid & 1) * 128 + wm + mf * 16 + hh * 8 + g] = rsum[mf][hh];
    }
    __syncthreads();
    if (tid < 128) {
        float iv = 1.0f / (rs[tid] + rs[128 + tid]);
        g_rinv[(size_t)bh * S + q0 + tid] = iv;
        sinv[tid] = iv;
    }
    __syncthreads();

    // scaled ctx -> g_ctx (fp16: consumed only by fc's fp16 MMA)
    const int b_ = bh >> 4, h_ = bh & 15;
#pragma unroll
    for (int mf = 0; mf < 2; mf++) {
        const int r0 = wm + mf * 16 + g;
        const float iv0 = sinv[r0], iv1 = sinv[r0 + 8];
#pragma unroll
        for (int nf = 0; nf < 4; nf++) {
            const int c0 = wn + nf * 8 + tq * 2;
            *(__half2*)&g_ctx[((size_t)b_ * S + q0 + r0) * D + h_ * DK + c0] =
                __floats2half2_rn(cacc[mf][nf][0] * iv0, cacc[mf][nf][1] * iv0);
            *(__half2*)&g_ctx[((size_t)b_ * S + q0 + r0 + 8) * D + h_ * DK + c0] =
                __floats2half2_rn(cacc[mf][nf][2] * iv1, cacc[mf][nf][3] * iv1);
        }
    }
}

// ---------------------------------------------------------------------------
// K3: normalize: attn_out[row][*] = half2float(g_eh[row][*]) * rinv[row]
// ---------------------------------------------------------------------------
__global__ __launch_bounds__(256) void attn_scale_kernel(float* __restrict__ attn)
{
    size_t idx4 = (size_t)blockIdx.x * blockDim.x + threadIdx.x;  // 4-elem idx
    size_t row  = idx4 >> 9;                                      // 512 groups/row
    float inv = g_rinv[row];
    uint2 e = __ldcs((const uint2*)g_eh + idx4);
    __half2 h0, h1;
    __builtin_memcpy(&h0, &e.x, 4);
    __builtin_memcpy(&h1, &e.y, 4);
    float2 f0 = __half22float2(h0);
    float2 f1 = __half22float2(h1);
    float4 v = make_float4(f0.x * inv, f0.y * inv, f1.x * inv, f1.y * inv);
    __stcs((float4*)attn + idx4, v);
}

// ---------------------------------------------------------------------------
// K5: LayerNorm over last dim (1024). One block (256 thr) per row.
// ---------------------------------------------------------------------------
__global__ __launch_bounds__(256) void ln_kernel(
    const float* __restrict__ gamma, const float* __restrict__ beta,
    float* __restrict__ out)
{
    __shared__ float s1[8], s2[8];
    __shared__ float sm_mean, sm_rstd;
    const int row = blockIdx.x;
    const int t   = threadIdx.x;
    const float* x = g_x + (size_t)row * D;

    float4 v = *(const float4*)(x + t * 4);
    float sum = v.x + v.y + v.z + v.w;
    float sq  = v.x * v.x + v.y * v.y + v.z * v.z + v.w * v.w;
#pragma unroll
    for (int m = 16; m >= 1; m >>= 1) {
        sum += __shfl_xor_sync(0xffffffffu, sum, m);
        sq  += __shfl_xor_sync(0xffffffffu, sq, m);
    }
    const int warp = t >> 5, lane = t & 31;
    if (lane == 0) { s1[warp] = sum; s2[warp] = sq; }
    __syncthreads();
    if (t == 0) {
        float a = 0.f, c = 0.f;
#pragma unroll
        for (int w = 0; w < 8; w++) { a += s1[w]; c += s2[w]; }
        float mean = a * (1.0f / D);
        float var  = c * (1.0f / D) - mean * mean;
        sm_mean = mean;
        sm_rstd = rsqrtf(var + 1e-6f);
    }
    __syncthreads();
    const float mean = sm_mean, r = sm_rstd;
    float4 g4 = *(const float4*)(gamma + t * 4);
    float4 b4 = *(const float4*)(beta + t * 4);
    float4 o;
    o.x = (v.x - mean) * r * g4.x + b4.x;
    o.y = (v.y - mean) * r * g4.y + b4.y;
    o.z = (v.z - mean) * r * g4.z + b4.z;
    o.w = (v.w - mean) * r * g4.w + b4.w;
    *(float4*)(out + (size_t)row * D + t * 4) = o;
}

// ---------------------------------------------------------------------------
extern "C" void kernel_launch(void* const* d_in, const int* in_sizes, int n_in,
                              void* d_out, int out_size)
{
    const float* q     = (const float*)d_in[0];
    const float* k     = (const float*)d_in[1];
    const float* v     = (const float*)d_in[2];
    const float* Wq    = (const float*)d_in[3];
    const float* bq    = (const float*)d_in[4];
    const float* Wfc   = (const float*)d_in[5];
    const float* bfc   = (const float*)d_in[6];
    const float* gamma = (const float*)d_in[7];
    const float* beta  = (const float*)d_in[8];

    float* out_x    = (float*)d_out;
    float* out_attn = out_x + X_ELEMS;

    cudaFuncSetAttribute(gemm_f16_kernel,
                         cudaFuncAttributeMaxDynamicSharedMemorySize, GEMM_SMEM);
    cudaFuncSetAttribute(attn_mma_kernel,
                         cudaFuncAttributeMaxDynamicSharedMemorySize, ATTN_SMEM);

    __half *qcv_p, *kcv_p, *vcv_p, *wqt_p, *wfct_p, *ctx_p;
    float *x_p;
    cudaGetSymbolAddress((void**)&qcv_p,  g_qcv);
    cudaGetSymbolAddress((void**)&kcv_p,  g_kcv);
    cudaGetSymbolAddress((void**)&vcv_p,  g_vcv);
    cudaGetSymbolAddress((void**)&wqt_p,  g_wqt);
    cudaGetSymbolAddress((void**)&wfct_p, g_wfct);
    cudaGetSymbolAddress((void**)&ctx_p,  g_ctx);
    cudaGetSymbolAddress((void**)&x_p,    g_x);

    convert_kernel<<<dim3((unsigned)(X_ELEMS / 4 / 256), 3), 256>>>(q, k, v);
    transpose_kernel<<<dim3(32, 32, 2), dim3(32, 8)>>>(Wq, Wfc);
    gemm_f16_kernel<<<dim3(8, 64, 3), 256, GEMM_SMEM>>>(
        qcv_p, kcv_p, vcv_p, wqt_p, bq, nullptr, nullptr, 0);
    attn_mma_kernel<<<dim3(16, 64), 256, ATTN_SMEM>>>();
    attn_scale_kernel<<<(unsigned)(ATTN_ELEMS / 4 / 256), 256>>>(out_attn);
    gemm_f16_kernel<<<dim3(8, 64, 1), 256, GEMM_SMEM>>>(
        ctx_p, ctx_p, ctx_p, wfct_p, bfc, q, x_p, 1);
    ln_kernel<<<B * S, 256>>>(gamma, beta, out_x);
}